// round 13
// baseline (speedup 1.0000x reference)
#include <cuda_runtime.h>
#include <cuda_bf16.h>
#include <math.h>
#include <stdint.h>

// LiquidNCPNetwork: persistent kernel, cells pipelined across steps.
// Phase p: cell1(p), cell2(p-1), cell3(p-2) — mutually independent.
// Work-stealing item queue per phase; last-split-finisher combines its tile
// inline (deterministic fixed-order sum); ONE grid barrier per phase.
// Math identical to R6-R12: bf16 hi/lo split, drop lo*lo term.

#define BATCH  64
#define SEQ    32
#define IN_F   512
#define INTER  1229
#define CMD    819
#define MOTOR  512
#define NUNITS 2560
#define YSZ    (BATCH * SEQ * MOTOR)

#define HPAD1 1280
#define KC1   1792
#define XCH1  8
#define HCH1  20
#define XPAD2 1280
#define HPAD2 832
#define KC2   2112
#define XCH2  20
#define HCH2  13
#define XPAD3 832
#define HPAD3 512
#define KC3   1344
#define XCH3  13
#define HCH3  8
#define JT1 77
#define JT2 52
#define JT3 32

#define KS1 4
#define KS2 5
#define KS3 3
#define I1 (JT1 * KS1)        // 308
#define I2 (JT2 * KS2)        // 260
#define I3 (JT3 * KS3)        // 96
#define SLOT1 0
#define SLOT2 I1
#define SLOT3 (I1 + I2)
#define NSLOTS (I1 + I2 + I3) // 664
#define NPH (SEQ + 2)         // 34 phases
#define NTC (JT1 + JT2 + JT3) // 161 tile counters
#define MAXGRID 512
#define NBSL 16

__device__ __align__(1024) __nv_bfloat16 g_wb1[(size_t)JT1 * 128 * KC1];
__device__ __align__(1024) __nv_bfloat16 g_wb2[(size_t)JT2 * 128 * KC2];
__device__ __align__(1024) __nv_bfloat16 g_wb3[(size_t)JT3 * 128 * KC3];
__device__ __align__(1024) __nv_bfloat16 g_x1[(size_t)SEQ * 128 * IN_F];
__device__ __align__(1024) __nv_bfloat16 g_z1h[2][128 * HPAD1];
__device__ __align__(1024) __nv_bfloat16 g_z2x[2][128 * XPAD2];
__device__ __align__(1024) __nv_bfloat16 g_z2h[2][128 * HPAD2];
__device__ __align__(1024) __nv_bfloat16 g_z3x[2][128 * XPAD3];
__device__ __align__(1024) __nv_bfloat16 g_z3h[2][128 * HPAD3];
__device__ __align__(16) float g_part[(size_t)NSLOTS * 128 * 64];
// queues + tile completion counters + barrier state (all zeroed by reset)
__device__ int g_q[NPH];
__device__ int g_tc[NTC];
__device__ int g_arr[NBSL * 32];
__device__ int g_top;
__device__ volatile int g_release;

#define SW128(o) ((o) ^ (((o) >> 3) & 0x70))
#define STAGE_BYTES 32768
#define SMEM_TOTAL  (3 * STAGE_BYTES)

__device__ __forceinline__ uint32_t s2u32(const void* p) {
    uint32_t a;
    asm("{ .reg .u64 t; cvta.to.shared.u64 t, %1; cvt.u32.u64 %0, t; }" : "=r"(a) : "l"(p));
    return a;
}
__device__ __forceinline__ void cpasync16(uint32_t s, const void* g) {
    asm volatile("cp.async.cg.shared.global [%0], [%1], 16;" :: "r"(s), "l"(g));
}
template<int N> __device__ __forceinline__ void waitgrp() {
    asm volatile("cp.async.wait_group %0;" :: "n"(N) : "memory");
}
__device__ __forceinline__ void ldm_x4(uint32_t& r0, uint32_t& r1, uint32_t& r2,
                                       uint32_t& r3, uint32_t addr) {
    asm volatile("ldmatrix.sync.aligned.m8n8.x4.shared.b16 {%0,%1,%2,%3}, [%4];"
                 : "=r"(r0), "=r"(r1), "=r"(r2), "=r"(r3) : "r"(addr));
}
__device__ __forceinline__ void mma16816(float* c, uint32_t a0, uint32_t a1, uint32_t a2,
                                         uint32_t a3, uint32_t b0, uint32_t b1) {
    asm volatile("mma.sync.aligned.m16n8k16.row.col.f32.bf16.bf16.f32 "
                 "{%0,%1,%2,%3}, {%4,%5,%6,%7}, {%8,%9}, {%0,%1,%2,%3};"
                 : "+f"(c[0]), "+f"(c[1]), "+f"(c[2]), "+f"(c[3])
                 : "r"(a0), "r"(a1), "r"(a2), "r"(a3), "r"(b0), "r"(b1));
}

__device__ __forceinline__ void gbar(int bid, int tid, int target, int nb) {
    __syncthreads();
    if (tid == 0) {
        __threadfence();
        int slot = bid & (NBSL - 1);
        int cnt = (nb - slot + NBSL - 1) / NBSL;
        int prev = atomicAdd(&g_arr[slot * 32], 1);
        if (prev == target * cnt - 1) {
            int pt = atomicAdd(&g_top, 1);
            if (pt == target * NBSL - 1) g_release = target;
        }
        while (g_release < target) { }
        __threadfence();
    }
    __syncthreads();
}

// ---------------- prep kernels ----------------
__global__ void prep_w_all(
    const float* __restrict__ Wg1, const float* __restrict__ Wh1,
    const float* __restrict__ Wfg1, const float* __restrict__ Wfh1,
    const float* __restrict__ M1,
    const float* __restrict__ Wg2, const float* __restrict__ Wh2,
    const float* __restrict__ Wfg2, const float* __restrict__ Wfh2,
    const float* __restrict__ M2,
    const float* __restrict__ Wg3, const float* __restrict__ Wh3,
    const float* __restrict__ Wfg3, const float* __restrict__ Wfh3,
    const float* __restrict__ M3)
{
    int blk = blockIdx.x;
    const float *Wg, *Wh, *Wfg, *Wfh, *M;
    __nv_bfloat16* dst;
    int N, Korig, xvalid, xpad, hvalid, Kc;
    if (blk < JT1 * 64) {
        Wg = Wg1; Wh = Wh1; Wfg = Wfg1; Wfh = Wfh1; M = M1; dst = g_wb1;
        N = INTER; Korig = IN_F + INTER; xvalid = IN_F; xpad = IN_F;
        hvalid = INTER; Kc = KC1;
    } else if (blk < (JT1 + JT2) * 64) {
        blk -= JT1 * 64;
        Wg = Wg2; Wh = Wh2; Wfg = Wfg2; Wfh = Wfh2; M = M2; dst = g_wb2;
        N = CMD; Korig = INTER + CMD; xvalid = INTER; xpad = XPAD2;
        hvalid = CMD; Kc = KC2;
    } else {
        blk -= (JT1 + JT2) * 64;
        Wg = Wg3; Wh = Wh3; Wfg = Wfg3; Wfh = Wfh3; M = M3; dst = g_wb3;
        N = MOTOR; Korig = CMD + MOTOR; xvalid = CMD; xpad = XPAD3;
        hvalid = MOTOR; Kc = KC3;
    }
    int n = blk * 2;
    int loc = n & 127;
    int j = (n >> 7) * 16 + (loc >> 3);
    int t = (loc >> 1) & 3;
    const float* W = (t == 0) ? Wg : (t == 1) ? Wh : (t == 2) ? Wfg : Wfh;
    __nv_bfloat16* d_hi = dst + (size_t)n * Kc;
    __nv_bfloat16* d_lo = d_hi + Kc;
    bool jok = (j < N);
    for (int k = threadIdx.x; k < Kc; k += 256) {
        float v = 0.f;
        if (jok) {
            int kin; bool ok;
            if (k < xpad) { kin = k; ok = (k < xvalid); }
            else { int hk = k - xpad; kin = xvalid + hk; ok = (hk < hvalid); }
            if (ok) v = W[(size_t)j * Korig + kin] * M[(size_t)j * Korig + kin];
        }
        __nv_bfloat16 hi = __float2bfloat16(v);
        d_hi[k] = hi;
        d_lo[k] = __float2bfloat16(v - __bfloat162float(hi));
    }
}

__global__ void prep_x_kernel(const float* __restrict__ x, __nv_bfloat16* __restrict__ dst)
{
    int idx = blockIdx.x * 256 + threadIdx.x;
    int b = idx >> 14, r = idx & 16383, s = r >> 9, f = r & 511;
    float v = x[idx];
    __nv_bfloat16 hi = __float2bfloat16(v);
    size_t base = (size_t)s * 128 * 512;
    dst[base + (size_t)b * 512 + f] = hi;
    dst[base + (size_t)(b + 64) * 512 + f] = __float2bfloat16(v - __bfloat162float(hi));
}

__global__ void prep_h0_kernel(const float* __restrict__ h0, __nv_bfloat16* __restrict__ z1,
                               __nv_bfloat16* __restrict__ z2, __nv_bfloat16* __restrict__ z3)
{
    int idx = blockIdx.x * 256 + threadIdx.x;
    int b = idx / NUNITS, u = idx % NUNITS;
    float v = h0[idx];
    __nv_bfloat16 hi = __float2bfloat16(v);
    __nv_bfloat16 lo = __float2bfloat16(v - __bfloat162float(hi));
    if (u < INTER)            { z1[(size_t)b*HPAD1+u] = hi; z1[(size_t)(b+64)*HPAD1+u] = lo; }
    else if (u < INTER + CMD) { int c = u - INTER;
                                z2[(size_t)b*HPAD2+c] = hi; z2[(size_t)(b+64)*HPAD2+c] = lo; }
    else                      { int c = u - INTER - CMD;
                                z3[(size_t)b*HPAD3+c] = hi; z3[(size_t)(b+64)*HPAD3+c] = lo; }
}

__global__ void reset_kernel() {
    int i = threadIdx.x;
    if (i < NPH) g_q[i] = 0;
    if (i < NTC) g_tc[i] = 0;
    if (i < NBSL * 32) g_arr[i] = 0;
    if (i == 0) { g_top = 0; g_release = 0; }
}

// ---------------- persistent scan kernel ----------------
__device__ __forceinline__ void compute_partial(
    uint32_t sb, int tid,
    const __nv_bfloat16* xpart, int xstride, int xchunks,
    const __nv_bfloat16* hpart, int hstride, int hchunks,
    const __nv_bfloat16* wbase, int wKc,
    int tile, int split, int ks, float* P)
{
    const int lane = tid & 31;
    const int wid  = tid >> 5;
    const int warprow = wid >> 2;
    const int warpcol = wid & 3;
    const int m_warp = warprow * 64;
    const int n_warp = warpcol * 32;
    const int C = xchunks + hchunks;
    const int c0 = (C * split) / ks;
    const int c1 = (C * (split + 1)) / ks;

    float acc[4][4][4];
    #pragma unroll
    for (int mt = 0; mt < 4; mt++)
        #pragma unroll
        for (int nt = 0; nt < 4; nt++)
            #pragma unroll
            for (int i = 0; i < 4; i++) acc[mt][nt][i] = 0.f;

    auto load_stage = [&](int c) {
        uint32_t abase = sb + (uint32_t)(c % 3) * STAGE_BYTES;
        uint32_t bbase = abase + 16384;
        const char* asrc; size_t astr;
        if (c < xchunks) { asrc = (const char*)xpart + (size_t)c * 128; astr = (size_t)xstride * 2; }
        else { asrc = (const char*)hpart + (size_t)(c - xchunks) * 128; astr = (size_t)hstride * 2; }
        const char* bsrc = (const char*)wbase
                         + ((size_t)tile * 128 * wKc + (size_t)c * 64) * 2;
        const size_t bstr = (size_t)wKc * 2;
        #pragma unroll
        for (int i = 0; i < 4; i++) {
            int g = i * 256 + tid;
            int row = g >> 3, col = g & 7;
            uint32_t off = (uint32_t)(row * 128 + col * 16);
            cpasync16(abase + SW128(off), asrc + (size_t)row * astr + col * 16);
            cpasync16(bbase + SW128(off), bsrc + (size_t)row * bstr + col * 16);
        }
        asm volatile("cp.async.commit_group;" ::: "memory");
    };

    load_stage(c0);
    if (c0 + 1 < c1) load_stage(c0 + 1);

    for (int c = c0; c < c1; c++) {
        if (c + 2 < c1) { load_stage(c + 2); waitgrp<2>(); }
        else if (c + 1 < c1) waitgrp<1>();
        else waitgrp<0>();
        __syncthreads();

        uint32_t abase = sb + (uint32_t)(c % 3) * STAGE_BYTES;
        uint32_t bbase = abase + 16384;
        #pragma unroll
        for (int ksi = 0; ksi < 4; ksi++) {
            int kb = ksi * 32 + (lane >> 4) * 16;
            uint32_t af[4][4];
            #pragma unroll
            for (int mt = 0; mt < 4; mt++) {
                uint32_t off = (uint32_t)((m_warp + mt * 16 + (lane & 15)) * 128 + kb);
                ldm_x4(af[mt][0], af[mt][1], af[mt][2], af[mt][3], abase + SW128(off));
            }
            uint32_t bf[4][2];
            #pragma unroll
            for (int np = 0; np < 2; np++) {
                uint32_t off = (uint32_t)((n_warp + np * 16 + (lane & 15)) * 128 + kb);
                uint32_t r0, r1, r2, r3;
                ldm_x4(r0, r1, r2, r3, bbase + SW128(off));
                bf[np * 2][0] = r0; bf[np * 2 + 1][0] = r1;
                bf[np * 2][1] = r2; bf[np * 2 + 1][1] = r3;
            }
            #pragma unroll
            for (int mt = 0; mt < 4; mt++)
                #pragma unroll
                for (int nt = 0; nt < 4; nt++)
                    mma16816(acc[mt][nt], af[mt][0], af[mt][1], af[mt][2], af[mt][3],
                             bf[nt][0], bf[nt][1]);
        }
        __syncthreads();
    }

    int hrow = lane >> 2, head = lane & 3;
    #pragma unroll
    for (int mt = 0; mt < 4; mt++) {
        #pragma unroll
        for (int nt = 0; nt < 4; nt++) {
            int col = (warpcol * 4 + nt) * 4 + head;
            int r0 = m_warp + mt * 16 + hrow;
            if (warprow == 0) {
                P[r0 * 64 + col] = acc[mt][nt][0] + acc[mt][nt][1];
                P[(r0 + 8) * 64 + col] = acc[mt][nt][2] + acc[mt][nt][3];
            } else {
                P[r0 * 64 + col] = acc[mt][nt][0];
                P[(r0 + 8) * 64 + col] = acc[mt][nt][2];
            }
        }
    }
}

__device__ __forceinline__ void combine_tile(
    int tid, const float* Pb, int tile, int ks, int N, float ts,
    const float* __restrict__ bg, const float* __restrict__ bh,
    const float* __restrict__ bfg, const float* __restrict__ bfh,
    __nv_bfloat16* znx, int znx_stride,
    __nv_bfloat16* zsh, int zsh_stride,
    float* yp, float* hfp, int hoff)
{
    #pragma unroll
    for (int q = 0; q < 4; q++) {
        int pair = q * 256 + tid;
        int b = pair >> 4;
        int jj = pair & 15;
        int j = tile * 16 + jj;
        if (j >= N) continue;
        float4 h4 = make_float4(0.f, 0.f, 0.f, 0.f);
        float4 l4 = make_float4(0.f, 0.f, 0.f, 0.f);
        for (int s = 0; s < ks; s++) {
            float4 a = __ldcg((const float4*)(Pb + (size_t)s * (128 * 64) + b * 64 + jj * 4));
            float4 c = __ldcg((const float4*)(Pb + (size_t)s * (128 * 64) + (b + 64) * 64 + jj * 4));
            h4.x += a.x; h4.y += a.y; h4.z += a.z; h4.w += a.w;
            l4.x += c.x; l4.y += c.y; l4.z += c.z; l4.w += c.w;
        }
        float a0 = h4.x + l4.x;
        float a1 = h4.y + l4.y;
        float a2 = h4.z + l4.z;
        float a3 = h4.w + l4.w;
        float g    = tanhf(a0 + bg[j]);
        float hh   = tanhf(a1 + bh[j]);
        float pre  = (a2 + bfg[j]) + ts * (a3 + bfh[j]);
        float gate = 1.f / (1.f + expf(-pre));
        float o    = g * (1.f - gate) + hh * gate;
        __nv_bfloat16 ohi = __float2bfloat16(o);
        __nv_bfloat16 olo = __float2bfloat16(o - __bfloat162float(ohi));
        if (znx) {
            znx[(size_t)b * znx_stride + j] = ohi;
            znx[(size_t)(b + 64) * znx_stride + j] = olo;
        }
        zsh[(size_t)b * zsh_stride + j] = ohi;
        zsh[(size_t)(b + 64) * zsh_stride + j] = olo;
        if (yp)  yp[(size_t)b * (SEQ * MOTOR) + j] = o;
        if (hfp) hfp[(size_t)b * NUNITS + hoff + j] = o;
    }
}

__global__ void __launch_bounds__(256, 2)
scan_kernel(int nb, const float* __restrict__ tsp,
            const float* __restrict__ bg1, const float* __restrict__ bh1,
            const float* __restrict__ bfg1, const float* __restrict__ bfh1,
            const float* __restrict__ bg2, const float* __restrict__ bh2,
            const float* __restrict__ bfg2, const float* __restrict__ bfh2,
            const float* __restrict__ bg3, const float* __restrict__ bh3,
            const float* __restrict__ bfg3, const float* __restrict__ bfh3,
            float* __restrict__ out)
{
    extern __shared__ char smem[];
    __shared__ int s_it, s_last;
    const uint32_t sb = s2u32(smem);
    const int tid = threadIdx.x;
    const int bid = blockIdx.x;
    int target = 0;

    for (int p = 0; p < NPH; p++) {
        const int s1 = p, s2 = p - 1, s3 = p - 2;
        const int n1 = (s1 < SEQ) ? I1 : 0;
        const int n2 = (s2 >= 0 && s2 < SEQ) ? I2 : 0;
        const int n3 = (s3 >= 0 && s3 < SEQ) ? I3 : 0;
        const int total = n1 + n2 + n3;
        // tile-counter targets (monotonic across phases)
        const int tgt1 = (s1 + 1) * KS1;
        const int tgt2 = (s2 + 1) * KS2;
        const int tgt3 = (s3 + 1) * KS3;

        while (true) {
            if (tid == 0) s_it = atomicAdd(&g_q[p], 1);
            __syncthreads();
            int it = s_it;
            __syncthreads();
            if (it >= total) break;

            int cell, tile, split, tcidx, tgt;
            if (it < n1)           { cell = 0; int li = it;
                                     tile = li / KS1; split = li % KS1;
                                     tcidx = tile; tgt = tgt1; }
            else if (it < n1 + n2) { cell = 1; int li = it - n1;
                                     tile = li / KS2; split = li % KS2;
                                     tcidx = JT1 + tile; tgt = tgt2; }
            else                   { cell = 2; int li = it - n1 - n2;
                                     tile = li / KS3; split = li % KS3;
                                     tcidx = JT1 + JT2 + tile; tgt = tgt3; }

            if (cell == 0) {
                compute_partial(sb, tid,
                    g_x1 + (size_t)s1 * 128 * IN_F, IN_F, XCH1,
                    g_z1h[s1 & 1], HPAD1, HCH1,
                    g_wb1, KC1, tile, split, KS1,
                    g_part + (size_t)(SLOT1 + tile * KS1 + split) * (128 * 64));
            } else if (cell == 1) {
                compute_partial(sb, tid,
                    g_z2x[s2 & 1], XPAD2, XCH2,
                    g_z2h[s2 & 1], HPAD2, HCH2,
                    g_wb2, KC2, tile, split, KS2,
                    g_part + (size_t)(SLOT2 + tile * KS2 + split) * (128 * 64));
            } else {
                compute_partial(sb, tid,
                    g_z3x[s3 & 1], XPAD3, XCH3,
                    g_z3h[s3 & 1], HPAD3, HCH3,
                    g_wb3, KC3, tile, split, KS3,
                    g_part + (size_t)(SLOT3 + tile * KS3 + split) * (128 * 64));
            }

            __threadfence();
            __syncthreads();
            if (tid == 0) {
                int prev = atomicAdd(&g_tc[tcidx], 1);
                s_last = (prev == tgt - 1);
            }
            __syncthreads();
            if (s_last) {
                __threadfence();   // acquire other splits' partials
                if (cell == 0) {
                    combine_tile(tid,
                        g_part + (size_t)(SLOT1 + tile * KS1) * (128 * 64),
                        tile, KS1, INTER, tsp[s1], bg1, bh1, bfg1, bfh1,
                        g_z2x[s1 & 1], XPAD2, g_z1h[(s1 + 1) & 1], HPAD1,
                        nullptr, (s1 == SEQ - 1) ? (out + YSZ) : nullptr, 0);
                } else if (cell == 1) {
                    combine_tile(tid,
                        g_part + (size_t)(SLOT2 + tile * KS2) * (128 * 64),
                        tile, KS2, CMD, tsp[s2], bg2, bh2, bfg2, bfh2,
                        g_z3x[s2 & 1], XPAD3, g_z2h[(s2 + 1) & 1], HPAD2,
                        nullptr, (s2 == SEQ - 1) ? (out + YSZ) : nullptr, INTER);
                } else {
                    combine_tile(tid,
                        g_part + (size_t)(SLOT3 + tile * KS3) * (128 * 64),
                        tile, KS3, MOTOR, tsp[s3], bg3, bh3, bfg3, bfh3,
                        nullptr, 0, g_z3h[(s3 + 1) & 1], HPAD3,
                        out + (size_t)s3 * MOTOR,
                        (s3 == SEQ - 1) ? (out + YSZ) : nullptr, INTER + CMD);
                }
            }
        }
        gbar(bid, tid, ++target, nb);
    }
}

// ---------------- host ----------------
extern "C" void kernel_launch(void* const* d_in, const int* in_sizes, int n_in,
                              void* d_out, int out_size)
{
    const float* x   = (const float*)d_in[0];
    const float* h0  = (const float*)d_in[1];
    const float* ts  = (const float*)d_in[2];
    const float *Wg1=(const float*)d_in[3], *Wh1=(const float*)d_in[4],
                *Wfg1=(const float*)d_in[5], *Wfh1=(const float*)d_in[6],
                *bg1=(const float*)d_in[7], *bh1=(const float*)d_in[8],
                *bfg1=(const float*)d_in[9], *bfh1=(const float*)d_in[10],
                *m1=(const float*)d_in[11];
    const float *Wg2=(const float*)d_in[12], *Wh2=(const float*)d_in[13],
                *Wfg2=(const float*)d_in[14], *Wfh2=(const float*)d_in[15],
                *bg2=(const float*)d_in[16], *bh2=(const float*)d_in[17],
                *bfg2=(const float*)d_in[18], *bfh2=(const float*)d_in[19],
                *m2=(const float*)d_in[20];
    const float *Wg3=(const float*)d_in[21], *Wh3=(const float*)d_in[22],
                *Wfg3=(const float*)d_in[23], *Wfh3=(const float*)d_in[24],
                *bg3=(const float*)d_in[25], *bh3=(const float*)d_in[26],
                *bfg3=(const float*)d_in[27], *bfh3=(const float*)d_in[28],
                *m3=(const float*)d_in[29];
    float* out = (float*)d_out;

    __nv_bfloat16 *x1, *z1h, *z2h, *z3h;
    cudaGetSymbolAddress((void**)&x1,  g_x1);
    cudaGetSymbolAddress((void**)&z1h, g_z1h);
    cudaGetSymbolAddress((void**)&z2h, g_z2h);
    cudaGetSymbolAddress((void**)&z3h, g_z3h);

    cudaFuncSetAttribute(scan_kernel, cudaFuncAttributeMaxDynamicSharedMemorySize,
                         SMEM_TOTAL);

    int nper = 1, nsm = 148;
    cudaOccupancyMaxActiveBlocksPerMultiprocessor(&nper, scan_kernel, 256, SMEM_TOTAL);
    cudaDeviceGetAttribute(&nsm, cudaDevAttrMultiProcessorCount, 0);
    if (nper < 1) nper = 1;
    int nb = nper * nsm;
    if (nb > MAXGRID) nb = MAXGRID;

    prep_w_all<<<(JT1 + JT2 + JT3) * 64, 256>>>(Wg1, Wh1, Wfg1, Wfh1, m1,
                                                Wg2, Wh2, Wfg2, Wfh2, m2,
                                                Wg3, Wh3, Wfg3, Wfh3, m3);
    prep_x_kernel<<<(BATCH * SEQ * IN_F) / 256, 256>>>(x, x1);
    prep_h0_kernel<<<(BATCH * NUNITS) / 256, 256>>>(h0, z1h, z2h, z3h);

    scan_kernel<<<nb, 256, SMEM_TOTAL>>>(nb, ts,
        bg1, bh1, bfg1, bfh1, bg2, bh2, bfg2, bfh2, bg3, bh3, bfg3, bfh3, out);

    reset_kernel<<<1, 512>>>();
}

// round 14
// speedup vs baseline: 1.2338x; 1.2338x over previous
#include <cuda_runtime.h>
#include <cuda_bf16.h>
#include <math.h>
#include <stdint.h>

// LiquidNCPNetwork: persistent kernel, cells pipelined across steps (R12
// skeleton) + chunk-balanced reflected-pair static schedule.
// Phase p: cell1(p), cell2(p-1), cell3(p-2) — mutually independent.
// Compute phase: pair-slot s handles items (s, TOT-1-s) -> heavy items pair
// with light ones. Then barrier, combine phase (fixed-order deterministic
// sum + CfC gating), barrier.
// Math identical to R6-R13: bf16 hi/lo split, drop lo*lo term.

#define BATCH  64
#define SEQ    32
#define IN_F   512
#define INTER  1229
#define CMD    819
#define MOTOR  512
#define NUNITS 2560
#define YSZ    (BATCH * SEQ * MOTOR)

#define HPAD1 1280
#define KC1   1792
#define XCH1  8
#define HCH1  20
#define XPAD2 1280
#define HPAD2 832
#define KC2   2112
#define XCH2  20
#define HCH2  13
#define XPAD3 832
#define HPAD3 512
#define KC3   1344
#define XCH3  13
#define HCH3  8
#define JT1 77
#define JT2 52
#define JT3 32

#define KS1 4
#define KS2 4
#define KS3 2
#define I1 (JT1 * KS1)        // 308, 7 chunks each
#define I2 (JT2 * KS2)        // 208, 8-9 chunks each
#define I3 (JT3 * KS3)        // 64, 10-11 chunks each
#define SLOT1 0
#define SLOT2 I1
#define SLOT3 (I1 + I2)
#define NSLOTS (I1 + I2 + I3) // 580
#define NPH (SEQ + 2)         // 34 phases
#define MAXGRID 512
#define NBSL 16

__device__ __align__(1024) __nv_bfloat16 g_wb1[(size_t)JT1 * 128 * KC1];
__device__ __align__(1024) __nv_bfloat16 g_wb2[(size_t)JT2 * 128 * KC2];
__device__ __align__(1024) __nv_bfloat16 g_wb3[(size_t)JT3 * 128 * KC3];
__device__ __align__(1024) __nv_bfloat16 g_x1[(size_t)SEQ * 128 * IN_F];
__device__ __align__(1024) __nv_bfloat16 g_z1h[2][128 * HPAD1];
__device__ __align__(1024) __nv_bfloat16 g_z2x[128 * XPAD2];
__device__ __align__(1024) __nv_bfloat16 g_z2h[2][128 * HPAD2];
__device__ __align__(1024) __nv_bfloat16 g_z3x[128 * XPAD3];
__device__ __align__(1024) __nv_bfloat16 g_z3h[2][128 * HPAD3];
__device__ __align__(16) float g_part[(size_t)NSLOTS * 128 * 64];
// barrier state (zeroed by reset_kernel)
__device__ int g_arr[NBSL * 32];
__device__ int g_top;
__device__ volatile int g_release;

#define SW128(o) ((o) ^ (((o) >> 3) & 0x70))
#define STAGE_BYTES 32768
#define SMEM_TOTAL  (3 * STAGE_BYTES)

__device__ __forceinline__ uint32_t s2u32(const void* p) {
    uint32_t a;
    asm("{ .reg .u64 t; cvta.to.shared.u64 t, %1; cvt.u32.u64 %0, t; }" : "=r"(a) : "l"(p));
    return a;
}
__device__ __forceinline__ void cpasync16(uint32_t s, const void* g) {
    asm volatile("cp.async.cg.shared.global [%0], [%1], 16;" :: "r"(s), "l"(g));
}
template<int N> __device__ __forceinline__ void waitgrp() {
    asm volatile("cp.async.wait_group %0;" :: "n"(N) : "memory");
}
__device__ __forceinline__ void ldm_x4(uint32_t& r0, uint32_t& r1, uint32_t& r2,
                                       uint32_t& r3, uint32_t addr) {
    asm volatile("ldmatrix.sync.aligned.m8n8.x4.shared.b16 {%0,%1,%2,%3}, [%4];"
                 : "=r"(r0), "=r"(r1), "=r"(r2), "=r"(r3) : "r"(addr));
}
__device__ __forceinline__ void mma16816(float* c, uint32_t a0, uint32_t a1, uint32_t a2,
                                         uint32_t a3, uint32_t b0, uint32_t b1) {
    asm volatile("mma.sync.aligned.m16n8k16.row.col.f32.bf16.bf16.f32 "
                 "{%0,%1,%2,%3}, {%4,%5,%6,%7}, {%8,%9}, {%0,%1,%2,%3};"
                 : "+f"(c[0]), "+f"(c[1]), "+f"(c[2]), "+f"(c[3])
                 : "r"(a0), "r"(a1), "r"(a2), "r"(a3), "r"(b0), "r"(b1));
}

__device__ __forceinline__ void gbar(int bid, int tid, int target, int nb) {
    __syncthreads();
    if (tid == 0) {
        __threadfence();
        int slot = bid & (NBSL - 1);
        int cnt = (nb - slot + NBSL - 1) / NBSL;
        int prev = atomicAdd(&g_arr[slot * 32], 1);
        if (prev == target * cnt - 1) {
            int pt = atomicAdd(&g_top, 1);
            if (pt == target * NBSL - 1) g_release = target;
        }
        while (g_release < target) { }
        __threadfence();
    }
    __syncthreads();
}

// ---------------- prep kernels ----------------
__global__ void prep_w_all(
    const float* __restrict__ Wg1, const float* __restrict__ Wh1,
    const float* __restrict__ Wfg1, const float* __restrict__ Wfh1,
    const float* __restrict__ M1,
    const float* __restrict__ Wg2, const float* __restrict__ Wh2,
    const float* __restrict__ Wfg2, const float* __restrict__ Wfh2,
    const float* __restrict__ M2,
    const float* __restrict__ Wg3, const float* __restrict__ Wh3,
    const float* __restrict__ Wfg3, const float* __restrict__ Wfh3,
    const float* __restrict__ M3)
{
    int blk = blockIdx.x;
    const float *Wg, *Wh, *Wfg, *Wfh, *M;
    __nv_bfloat16* dst;
    int N, Korig, xvalid, xpad, hvalid, Kc;
    if (blk < JT1 * 64) {
        Wg = Wg1; Wh = Wh1; Wfg = Wfg1; Wfh = Wfh1; M = M1; dst = g_wb1;
        N = INTER; Korig = IN_F + INTER; xvalid = IN_F; xpad = IN_F;
        hvalid = INTER; Kc = KC1;
    } else if (blk < (JT1 + JT2) * 64) {
        blk -= JT1 * 64;
        Wg = Wg2; Wh = Wh2; Wfg = Wfg2; Wfh = Wfh2; M = M2; dst = g_wb2;
        N = CMD; Korig = INTER + CMD; xvalid = INTER; xpad = XPAD2;
        hvalid = CMD; Kc = KC2;
    } else {
        blk -= (JT1 + JT2) * 64;
        Wg = Wg3; Wh = Wh3; Wfg = Wfg3; Wfh = Wfh3; M = M3; dst = g_wb3;
        N = MOTOR; Korig = CMD + MOTOR; xvalid = CMD; xpad = XPAD3;
        hvalid = MOTOR; Kc = KC3;
    }
    int n = blk * 2;
    int loc = n & 127;
    int j = (n >> 7) * 16 + (loc >> 3);
    int t = (loc >> 1) & 3;
    const float* W = (t == 0) ? Wg : (t == 1) ? Wh : (t == 2) ? Wfg : Wfh;
    __nv_bfloat16* d_hi = dst + (size_t)n * Kc;
    __nv_bfloat16* d_lo = d_hi + Kc;
    bool jok = (j < N);
    for (int k = threadIdx.x; k < Kc; k += 256) {
        float v = 0.f;
        if (jok) {
            int kin; bool ok;
            if (k < xpad) { kin = k; ok = (k < xvalid); }
            else { int hk = k - xpad; kin = xvalid + hk; ok = (hk < hvalid); }
            if (ok) v = W[(size_t)j * Korig + kin] * M[(size_t)j * Korig + kin];
        }
        __nv_bfloat16 hi = __float2bfloat16(v);
        d_hi[k] = hi;
        d_lo[k] = __float2bfloat16(v - __bfloat162float(hi));
    }
}

__global__ void prep_x_kernel(const float* __restrict__ x, __nv_bfloat16* __restrict__ dst)
{
    int idx = blockIdx.x * 256 + threadIdx.x;
    int b = idx >> 14, r = idx & 16383, s = r >> 9, f = r & 511;
    float v = x[idx];
    __nv_bfloat16 hi = __float2bfloat16(v);
    size_t base = (size_t)s * 128 * 512;
    dst[base + (size_t)b * 512 + f] = hi;
    dst[base + (size_t)(b + 64) * 512 + f] = __float2bfloat16(v - __bfloat162float(hi));
}

__global__ void prep_h0_kernel(const float* __restrict__ h0, __nv_bfloat16* __restrict__ z1,
                               __nv_bfloat16* __restrict__ z2, __nv_bfloat16* __restrict__ z3)
{
    int idx = blockIdx.x * 256 + threadIdx.x;
    int b = idx / NUNITS, u = idx % NUNITS;
    float v = h0[idx];
    __nv_bfloat16 hi = __float2bfloat16(v);
    __nv_bfloat16 lo = __float2bfloat16(v - __bfloat162float(hi));
    if (u < INTER)            { z1[(size_t)b*HPAD1+u] = hi; z1[(size_t)(b+64)*HPAD1+u] = lo; }
    else if (u < INTER + CMD) { int c = u - INTER;
                                z2[(size_t)b*HPAD2+c] = hi; z2[(size_t)(b+64)*HPAD2+c] = lo; }
    else                      { int c = u - INTER - CMD;
                                z3[(size_t)b*HPAD3+c] = hi; z3[(size_t)(b+64)*HPAD3+c] = lo; }
}

__global__ void reset_kernel() {
    int i = threadIdx.x;
    if (i < NBSL * 32) g_arr[i] = 0;
    if (i == 0) { g_top = 0; g_release = 0; }
}

// ---------------- persistent scan kernel ----------------
__device__ __forceinline__ void compute_partial(
    uint32_t sb, int tid,
    const __nv_bfloat16* xpart, int xstride, int xchunks,
    const __nv_bfloat16* hpart, int hstride, int hchunks,
    const __nv_bfloat16* wbase, int wKc,
    int tile, int split, int ks, float* P)
{
    const int lane = tid & 31;
    const int wid  = tid >> 5;
    const int warprow = wid >> 2;
    const int warpcol = wid & 3;
    const int m_warp = warprow * 64;
    const int n_warp = warpcol * 32;
    const int C = xchunks + hchunks;
    const int c0 = (C * split) / ks;
    const int c1 = (C * (split + 1)) / ks;

    float acc[4][4][4];
    #pragma unroll
    for (int mt = 0; mt < 4; mt++)
        #pragma unroll
        for (int nt = 0; nt < 4; nt++)
            #pragma unroll
            for (int i = 0; i < 4; i++) acc[mt][nt][i] = 0.f;

    auto load_stage = [&](int c) {
        uint32_t abase = sb + (uint32_t)(c % 3) * STAGE_BYTES;
        uint32_t bbase = abase + 16384;
        const char* asrc; size_t astr;
        if (c < xchunks) { asrc = (const char*)xpart + (size_t)c * 128; astr = (size_t)xstride * 2; }
        else { asrc = (const char*)hpart + (size_t)(c - xchunks) * 128; astr = (size_t)hstride * 2; }
        const char* bsrc = (const char*)wbase
                         + ((size_t)tile * 128 * wKc + (size_t)c * 64) * 2;
        const size_t bstr = (size_t)wKc * 2;
        #pragma unroll
        for (int i = 0; i < 4; i++) {
            int g = i * 256 + tid;
            int row = g >> 3, col = g & 7;
            uint32_t off = (uint32_t)(row * 128 + col * 16);
            cpasync16(abase + SW128(off), asrc + (size_t)row * astr + col * 16);
            cpasync16(bbase + SW128(off), bsrc + (size_t)row * bstr + col * 16);
        }
        asm volatile("cp.async.commit_group;" ::: "memory");
    };

    load_stage(c0);
    if (c0 + 1 < c1) load_stage(c0 + 1);

    for (int c = c0; c < c1; c++) {
        if (c + 2 < c1) { load_stage(c + 2); waitgrp<2>(); }
        else if (c + 1 < c1) waitgrp<1>();
        else waitgrp<0>();
        __syncthreads();

        uint32_t abase = sb + (uint32_t)(c % 3) * STAGE_BYTES;
        uint32_t bbase = abase + 16384;
        #pragma unroll
        for (int ksi = 0; ksi < 4; ksi++) {
            int kb = ksi * 32 + (lane >> 4) * 16;
            uint32_t af[4][4];
            #pragma unroll
            for (int mt = 0; mt < 4; mt++) {
                uint32_t off = (uint32_t)((m_warp + mt * 16 + (lane & 15)) * 128 + kb);
                ldm_x4(af[mt][0], af[mt][1], af[mt][2], af[mt][3], abase + SW128(off));
            }
            uint32_t bf[4][2];
            #pragma unroll
            for (int np = 0; np < 2; np++) {
                uint32_t off = (uint32_t)((n_warp + np * 16 + (lane & 15)) * 128 + kb);
                uint32_t r0, r1, r2, r3;
                ldm_x4(r0, r1, r2, r3, bbase + SW128(off));
                bf[np * 2][0] = r0; bf[np * 2 + 1][0] = r1;
                bf[np * 2][1] = r2; bf[np * 2 + 1][1] = r3;
            }
            #pragma unroll
            for (int mt = 0; mt < 4; mt++)
                #pragma unroll
                for (int nt = 0; nt < 4; nt++)
                    mma16816(acc[mt][nt], af[mt][0], af[mt][1], af[mt][2], af[mt][3],
                             bf[nt][0], bf[nt][1]);
        }
        __syncthreads();
    }

    int hrow = lane >> 2, head = lane & 3;
    #pragma unroll
    for (int mt = 0; mt < 4; mt++) {
        #pragma unroll
        for (int nt = 0; nt < 4; nt++) {
            int col = (warpcol * 4 + nt) * 4 + head;
            int r0 = m_warp + mt * 16 + hrow;
            if (warprow == 0) {
                P[r0 * 64 + col] = acc[mt][nt][0] + acc[mt][nt][1];
                P[(r0 + 8) * 64 + col] = acc[mt][nt][2] + acc[mt][nt][3];
            } else {
                P[r0 * 64 + col] = acc[mt][nt][0];
                P[(r0 + 8) * 64 + col] = acc[mt][nt][2];
            }
        }
    }
}

// process one compute item by global item id
__device__ __forceinline__ void do_item(
    uint32_t sb, int tid, int it, int n1, int n2, int s1, int s2, int s3)
{
    if (it < n1) {
        int tile = it / KS1, split = it % KS1;
        compute_partial(sb, tid,
            g_x1 + (size_t)s1 * 128 * IN_F, IN_F, XCH1,
            g_z1h[s1 & 1], HPAD1, HCH1,
            g_wb1, KC1, tile, split, KS1,
            g_part + (size_t)(SLOT1 + tile * KS1 + split) * (128 * 64));
    } else if (it < n1 + n2) {
        int li = it - n1;
        int tile = li / KS2, split = li % KS2;
        compute_partial(sb, tid,
            g_z2x, XPAD2, XCH2,
            g_z2h[s2 & 1], HPAD2, HCH2,
            g_wb2, KC2, tile, split, KS2,
            g_part + (size_t)(SLOT2 + tile * KS2 + split) * (128 * 64));
    } else {
        int li = it - n1 - n2;
        int tile = li / KS3, split = li % KS3;
        compute_partial(sb, tid,
            g_z3x, XPAD3, XCH3,
            g_z3h[s3 & 1], HPAD3, HCH3,
            g_wb3, KC3, tile, split, KS3,
            g_part + (size_t)(SLOT3 + tile * KS3 + split) * (128 * 64));
    }
}

__device__ __forceinline__ void combine_q(
    int tid, const float* Pb, int tile, int quarter, int ks, int N, float ts,
    const float* __restrict__ bg, const float* __restrict__ bh,
    const float* __restrict__ bfg, const float* __restrict__ bfh,
    __nv_bfloat16* znx, int znx_stride,
    __nv_bfloat16* zsh, int zsh_stride,
    float* yp, float* hfp, int hoff)
{
    int pair = quarter * 256 + tid;
    int b = pair >> 4;
    int jj = pair & 15;
    int j = tile * 16 + jj;
    if (j >= N) return;
    float4 h4 = make_float4(0.f, 0.f, 0.f, 0.f);
    float4 l4 = make_float4(0.f, 0.f, 0.f, 0.f);
    for (int s = 0; s < ks; s++) {
        float4 a = __ldcg((const float4*)(Pb + (size_t)s * (128 * 64) + b * 64 + jj * 4));
        float4 c = __ldcg((const float4*)(Pb + (size_t)s * (128 * 64) + (b + 64) * 64 + jj * 4));
        h4.x += a.x; h4.y += a.y; h4.z += a.z; h4.w += a.w;
        l4.x += c.x; l4.y += c.y; l4.z += c.z; l4.w += c.w;
    }
    float a0 = h4.x + l4.x;
    float a1 = h4.y + l4.y;
    float a2 = h4.z + l4.z;
    float a3 = h4.w + l4.w;
    float g    = tanhf(a0 + bg[j]);
    float hh   = tanhf(a1 + bh[j]);
    float pre  = (a2 + bfg[j]) + ts * (a3 + bfh[j]);
    float gate = 1.f / (1.f + expf(-pre));
    float o    = g * (1.f - gate) + hh * gate;
    __nv_bfloat16 ohi = __float2bfloat16(o);
    __nv_bfloat16 olo = __float2bfloat16(o - __bfloat162float(ohi));
    if (znx) {
        znx[(size_t)b * znx_stride + j] = ohi;
        znx[(size_t)(b + 64) * znx_stride + j] = olo;
    }
    zsh[(size_t)b * zsh_stride + j] = ohi;
    zsh[(size_t)(b + 64) * zsh_stride + j] = olo;
    if (yp)  yp[(size_t)b * (SEQ * MOTOR) + j] = o;
    if (hfp) hfp[(size_t)b * NUNITS + hoff + j] = o;
}

__global__ void __launch_bounds__(256, 2)
scan_kernel(int nb, const float* __restrict__ tsp,
            const float* __restrict__ bg1, const float* __restrict__ bh1,
            const float* __restrict__ bfg1, const float* __restrict__ bfh1,
            const float* __restrict__ bg2, const float* __restrict__ bh2,
            const float* __restrict__ bfg2, const float* __restrict__ bfh2,
            const float* __restrict__ bg3, const float* __restrict__ bh3,
            const float* __restrict__ bfg3, const float* __restrict__ bfh3,
            float* __restrict__ out)
{
    extern __shared__ char smem[];
    const uint32_t sb = s2u32(smem);
    const int tid = threadIdx.x;
    const int bid = blockIdx.x;
    int target = 0;

    for (int p = 0; p < NPH; p++) {
        const int s1 = p, s2 = p - 1, s3 = p - 2;
        const bool a1 = (s1 < SEQ);
        const bool a2 = (s2 >= 0 && s2 < SEQ);
        const bool a3 = (s3 >= 0 && s3 < SEQ);
        const int n1 = a1 ? I1 : 0;
        const int n2 = a2 ? I2 : 0;
        const int n3 = a3 ? I3 : 0;
        const int total = n1 + n2 + n3;
        const int npairs = (total + 1) >> 1;

        // ---- compute phase: reflected-pair schedule (heavy pairs light) ----
        for (int sl = bid; sl < npairs; sl += nb) {
            int i1 = sl;
            int i2 = total - 1 - sl;
            do_item(sb, tid, i1, n1, n2, s1, s2, s3);
            if (i2 != i1) do_item(sb, tid, i2, n1, n2, s1, s2, s3);
        }
        gbar(bid, tid, ++target, nb);

        // ---- combine phase ----
        const int c1n = a1 ? JT1 * 4 : 0;
        const int c2n = a2 ? JT2 * 4 : 0;
        const int c3n = a3 ? JT3 * 4 : 0;
        const int ctotal = c1n + c2n + c3n;
        for (int it = bid; it < ctotal; it += nb) {
            if (it < c1n) {
                int tile = it >> 2, q = it & 3;
                combine_q(tid, g_part + (size_t)(SLOT1 + tile * KS1) * (128 * 64),
                          tile, q, KS1, INTER, tsp[s1], bg1, bh1, bfg1, bfh1,
                          g_z2x, XPAD2, g_z1h[(s1 + 1) & 1], HPAD1,
                          nullptr, (s1 == SEQ - 1) ? (out + YSZ) : nullptr, 0);
            } else if (it < c1n + c2n) {
                int li = it - c1n;
                int tile = li >> 2, q = li & 3;
                combine_q(tid, g_part + (size_t)(SLOT2 + tile * KS2) * (128 * 64),
                          tile, q, KS2, CMD, tsp[s2], bg2, bh2, bfg2, bfh2,
                          g_z3x, XPAD3, g_z2h[(s2 + 1) & 1], HPAD2,
                          nullptr, (s2 == SEQ - 1) ? (out + YSZ) : nullptr, INTER);
            } else {
                int li = it - c1n - c2n;
                int tile = li >> 2, q = li & 3;
                combine_q(tid, g_part + (size_t)(SLOT3 + tile * KS3) * (128 * 64),
                          tile, q, KS3, MOTOR, tsp[s3], bg3, bh3, bfg3, bfh3,
                          nullptr, 0, g_z3h[(s3 + 1) & 1], HPAD3,
                          out + (size_t)s3 * MOTOR,
                          (s3 == SEQ - 1) ? (out + YSZ) : nullptr, INTER + CMD);
            }
        }
        gbar(bid, tid, ++target, nb);
    }
}

// ---------------- host ----------------
extern "C" void kernel_launch(void* const* d_in, const int* in_sizes, int n_in,
                              void* d_out, int out_size)
{
    const float* x   = (const float*)d_in[0];
    const float* h0  = (const float*)d_in[1];
    const float* ts  = (const float*)d_in[2];
    const float *Wg1=(const float*)d_in[3], *Wh1=(const float*)d_in[4],
                *Wfg1=(const float*)d_in[5], *Wfh1=(const float*)d_in[6],
                *bg1=(const float*)d_in[7], *bh1=(const float*)d_in[8],
                *bfg1=(const float*)d_in[9], *bfh1=(const float*)d_in[10],
                *m1=(const float*)d_in[11];
    const float *Wg2=(const float*)d_in[12], *Wh2=(const float*)d_in[13],
                *Wfg2=(const float*)d_in[14], *Wfh2=(const float*)d_in[15],
                *bg2=(const float*)d_in[16], *bh2=(const float*)d_in[17],
                *bfg2=(const float*)d_in[18], *bfh2=(const float*)d_in[19],
                *m2=(const float*)d_in[20];
    const float *Wg3=(const float*)d_in[21], *Wh3=(const float*)d_in[22],
                *Wfg3=(const float*)d_in[23], *Wfh3=(const float*)d_in[24],
                *bg3=(const float*)d_in[25], *bh3=(const float*)d_in[26],
                *bfg3=(const float*)d_in[27], *bfh3=(const float*)d_in[28],
                *m3=(const float*)d_in[29];
    float* out = (float*)d_out;

    __nv_bfloat16 *x1, *z1h, *z2h, *z3h;
    cudaGetSymbolAddress((void**)&x1,  g_x1);
    cudaGetSymbolAddress((void**)&z1h, g_z1h);
    cudaGetSymbolAddress((void**)&z2h, g_z2h);
    cudaGetSymbolAddress((void**)&z3h, g_z3h);

    cudaFuncSetAttribute(scan_kernel, cudaFuncAttributeMaxDynamicSharedMemorySize,
                         SMEM_TOTAL);

    int nper = 1, nsm = 148;
    cudaOccupancyMaxActiveBlocksPerMultiprocessor(&nper, scan_kernel, 256, SMEM_TOTAL);
    cudaDeviceGetAttribute(&nsm, cudaDevAttrMultiProcessorCount, 0);
    if (nper < 1) nper = 1;
    int nb = nper * nsm;
    if (nb > MAXGRID) nb = MAXGRID;

    prep_w_all<<<(JT1 + JT2 + JT3) * 64, 256>>>(Wg1, Wh1, Wfg1, Wfh1, m1,
                                                Wg2, Wh2, Wfg2, Wfh2, m2,
                                                Wg3, Wh3, Wfg3, Wfh3, m3);
    prep_x_kernel<<<(BATCH * SEQ * IN_F) / 256, 256>>>(x, x1);
    prep_h0_kernel<<<(BATCH * NUNITS) / 256, 256>>>(h0, z1h, z2h, z3h);

    scan_kernel<<<nb, 256, SMEM_TOTAL>>>(nb, ts,
        bg1, bh1, bfg1, bfh1, bg2, bh2, bfg2, bfh2, bg3, bh3, bfg3, bfh3, out);

    reset_kernel<<<1, 512>>>();
}

// round 16
// speedup vs baseline: 1.2566x; 1.0185x over previous
#include <cuda_runtime.h>
#include <cuda_bf16.h>
#include <math.h>
#include <stdint.h>

// LiquidNCPNetwork: persistent kernel, cells pipelined across steps (R12
// skeleton: strided schedule, separate combine phase, 2 barriers/phase)
// + single-sync chunk mainloop (R15): waitgrp -> sync -> issue load(c+2)
// -> mma(c). One __syncthreads per chunk instead of two; cp.async issue
// overlaps MMA.
// Math identical to R6-R14: bf16 hi/lo split, drop lo*lo term.

#define BATCH  64
#define SEQ    32
#define IN_F   512
#define INTER  1229
#define CMD    819
#define MOTOR  512
#define NUNITS 2560
#define YSZ    (BATCH * SEQ * MOTOR)

#define HPAD1 1280
#define KC1   1792
#define XCH1  8
#define HCH1  20
#define XPAD2 1280
#define HPAD2 832
#define KC2   2112
#define XCH2  20
#define HCH2  13
#define XPAD3 832
#define HPAD3 512
#define KC3   1344
#define XCH3  13
#define HCH3  8
#define JT1 77
#define JT2 52
#define JT3 32

#define KS1 4
#define KS2 5
#define KS3 3
#define I1 (JT1 * KS1)        // 308
#define I2 (JT2 * KS2)        // 260
#define I3 (JT3 * KS3)        // 96
#define SLOT1 0
#define SLOT2 I1
#define SLOT3 (I1 + I2)
#define NSLOTS (I1 + I2 + I3) // 664
#define NPH (SEQ + 2)         // 34 phases
#define MAXGRID 512
#define NBSL 16

__device__ __align__(1024) __nv_bfloat16 g_wb1[(size_t)JT1 * 128 * KC1];
__device__ __align__(1024) __nv_bfloat16 g_wb2[(size_t)JT2 * 128 * KC2];
__device__ __align__(1024) __nv_bfloat16 g_wb3[(size_t)JT3 * 128 * KC3];
__device__ __align__(1024) __nv_bfloat16 g_x1[(size_t)SEQ * 128 * IN_F];
__device__ __align__(1024) __nv_bfloat16 g_z1h[2][128 * HPAD1];
__device__ __align__(1024) __nv_bfloat16 g_z2x[128 * XPAD2];
__device__ __align__(1024) __nv_bfloat16 g_z2h[2][128 * HPAD2];
__device__ __align__(1024) __nv_bfloat16 g_z3x[128 * XPAD3];
__device__ __align__(1024) __nv_bfloat16 g_z3h[2][128 * HPAD3];
__device__ __align__(16) float g_part[(size_t)NSLOTS * 128 * 64];
// barrier state (zeroed by reset_kernel)
__device__ int g_arr[NBSL * 32];
__device__ int g_top;
__device__ volatile int g_release;

#define SW128(o) ((o) ^ (((o) >> 3) & 0x70))
#define STAGE_BYTES 32768
#define SMEM_TOTAL  (3 * STAGE_BYTES)

__device__ __forceinline__ uint32_t s2u32(const void* p) {
    uint32_t a;
    asm("{ .reg .u64 t; cvta.to.shared.u64 t, %1; cvt.u32.u64 %0, t; }" : "=r"(a) : "l"(p));
    return a;
}
__device__ __forceinline__ void cpasync16(uint32_t s, const void* g) {
    asm volatile("cp.async.cg.shared.global [%0], [%1], 16;" :: "r"(s), "l"(g));
}
template<int N> __device__ __forceinline__ void waitgrp() {
    asm volatile("cp.async.wait_group %0;" :: "n"(N) : "memory");
}
__device__ __forceinline__ void ldm_x4(uint32_t& r0, uint32_t& r1, uint32_t& r2,
                                       uint32_t& r3, uint32_t addr) {
    asm volatile("ldmatrix.sync.aligned.m8n8.x4.shared.b16 {%0,%1,%2,%3}, [%4];"
                 : "=r"(r0), "=r"(r1), "=r"(r2), "=r"(r3) : "r"(addr));
}
__device__ __forceinline__ void mma16816(float* c, uint32_t a0, uint32_t a1, uint32_t a2,
                                         uint32_t a3, uint32_t b0, uint32_t b1) {
    asm volatile("mma.sync.aligned.m16n8k16.row.col.f32.bf16.bf16.f32 "
                 "{%0,%1,%2,%3}, {%4,%5,%6,%7}, {%8,%9}, {%0,%1,%2,%3};"
                 : "+f"(c[0]), "+f"(c[1]), "+f"(c[2]), "+f"(c[3])
                 : "r"(a0), "r"(a1), "r"(a2), "r"(a3), "r"(b0), "r"(b1));
}

__device__ __forceinline__ void gbar(int bid, int tid, int target, int nb) {
    __syncthreads();
    if (tid == 0) {
        __threadfence();
        int slot = bid & (NBSL - 1);
        int cnt = (nb - slot + NBSL - 1) / NBSL;
        int prev = atomicAdd(&g_arr[slot * 32], 1);
        if (prev == target * cnt - 1) {
            int pt = atomicAdd(&g_top, 1);
            if (pt == target * NBSL - 1) g_release = target;
        }
        while (g_release < target) { }
        __threadfence();
    }
    __syncthreads();
}

// ---------------- prep kernels ----------------
__global__ void prep_w_all(
    const float* __restrict__ Wg1, const float* __restrict__ Wh1,
    const float* __restrict__ Wfg1, const float* __restrict__ Wfh1,
    const float* __restrict__ M1,
    const float* __restrict__ Wg2, const float* __restrict__ Wh2,
    const float* __restrict__ Wfg2, const float* __restrict__ Wfh2,
    const float* __restrict__ M2,
    const float* __restrict__ Wg3, const float* __restrict__ Wh3,
    const float* __restrict__ Wfg3, const float* __restrict__ Wfh3,
    const float* __restrict__ M3)
{
    int blk = blockIdx.x;
    const float *Wg, *Wh, *Wfg, *Wfh, *M;
    __nv_bfloat16* dst;
    int N, Korig, xvalid, xpad, hvalid, Kc;
    if (blk < JT1 * 64) {
        Wg = Wg1; Wh = Wh1; Wfg = Wfg1; Wfh = Wfh1; M = M1; dst = g_wb1;
        N = INTER; Korig = IN_F + INTER; xvalid = IN_F; xpad = IN_F;
        hvalid = INTER; Kc = KC1;
    } else if (blk < (JT1 + JT2) * 64) {
        blk -= JT1 * 64;
        Wg = Wg2; Wh = Wh2; Wfg = Wfg2; Wfh = Wfh2; M = M2; dst = g_wb2;
        N = CMD; Korig = INTER + CMD; xvalid = INTER; xpad = XPAD2;
        hvalid = CMD; Kc = KC2;
    } else {
        blk -= (JT1 + JT2) * 64;
        Wg = Wg3; Wh = Wh3; Wfg = Wfg3; Wfh = Wfh3; M = M3; dst = g_wb3;
        N = MOTOR; Korig = CMD + MOTOR; xvalid = CMD; xpad = XPAD3;
        hvalid = MOTOR; Kc = KC3;
    }
    int n = blk * 2;
    int loc = n & 127;
    int j = (n >> 7) * 16 + (loc >> 3);
    int t = (loc >> 1) & 3;
    const float* W = (t == 0) ? Wg : (t == 1) ? Wh : (t == 2) ? Wfg : Wfh;
    __nv_bfloat16* d_hi = dst + (size_t)n * Kc;
    __nv_bfloat16* d_lo = d_hi + Kc;
    bool jok = (j < N);
    for (int k = threadIdx.x; k < Kc; k += 256) {
        float v = 0.f;
        if (jok) {
            int kin; bool ok;
            if (k < xpad) { kin = k; ok = (k < xvalid); }
            else { int hk = k - xpad; kin = xvalid + hk; ok = (hk < hvalid); }
            if (ok) v = W[(size_t)j * Korig + kin] * M[(size_t)j * Korig + kin];
        }
        __nv_bfloat16 hi = __float2bfloat16(v);
        d_hi[k] = hi;
        d_lo[k] = __float2bfloat16(v - __bfloat162float(hi));
    }
}

__global__ void prep_x_kernel(const float* __restrict__ x, __nv_bfloat16* __restrict__ dst)
{
    int idx = blockIdx.x * 256 + threadIdx.x;
    int b = idx >> 14, r = idx & 16383, s = r >> 9, f = r & 511;
    float v = x[idx];
    __nv_bfloat16 hi = __float2bfloat16(v);
    size_t base = (size_t)s * 128 * 512;
    dst[base + (size_t)b * 512 + f] = hi;
    dst[base + (size_t)(b + 64) * 512 + f] = __float2bfloat16(v - __bfloat162float(hi));
}

__global__ void prep_h0_kernel(const float* __restrict__ h0, __nv_bfloat16* __restrict__ z1,
                               __nv_bfloat16* __restrict__ z2, __nv_bfloat16* __restrict__ z3)
{
    int idx = blockIdx.x * 256 + threadIdx.x;
    int b = idx / NUNITS, u = idx % NUNITS;
    float v = h0[idx];
    __nv_bfloat16 hi = __float2bfloat16(v);
    __nv_bfloat16 lo = __float2bfloat16(v - __bfloat162float(hi));
    if (u < INTER)            { z1[(size_t)b*HPAD1+u] = hi; z1[(size_t)(b+64)*HPAD1+u] = lo; }
    else if (u < INTER + CMD) { int c = u - INTER;
                                z2[(size_t)b*HPAD2+c] = hi; z2[(size_t)(b+64)*HPAD2+c] = lo; }
    else                      { int c = u - INTER - CMD;
                                z3[(size_t)b*HPAD3+c] = hi; z3[(size_t)(b+64)*HPAD3+c] = lo; }
}

__global__ void reset_kernel() {
    int i = threadIdx.x;
    if (i < NBSL * 32) g_arr[i] = 0;
    if (i == 0) { g_top = 0; g_release = 0; }
}

// ---------------- persistent scan kernel ----------------
__device__ __forceinline__ void compute_partial(
    uint32_t sb, int tid,
    const __nv_bfloat16* xpart, int xstride, int xchunks,
    const __nv_bfloat16* hpart, int hstride, int hchunks,
    const __nv_bfloat16* wbase, int wKc,
    int tile, int split, int ks, float* P)
{
    const int lane = tid & 31;
    const int wid  = tid >> 5;
    const int warprow = wid >> 2;
    const int warpcol = wid & 3;
    const int m_warp = warprow * 64;
    const int n_warp = warpcol * 32;
    const int C = xchunks + hchunks;
    const int c0 = (C * split) / ks;
    const int c1 = (C * (split + 1)) / ks;

    float acc[4][4][4];
    #pragma unroll
    for (int mt = 0; mt < 4; mt++)
        #pragma unroll
        for (int nt = 0; nt < 4; nt++)
            #pragma unroll
            for (int i = 0; i < 4; i++) acc[mt][nt][i] = 0.f;

    auto load_stage = [&](int c) {
        uint32_t abase = sb + (uint32_t)(c % 3) * STAGE_BYTES;
        uint32_t bbase = abase + 16384;
        const char* asrc; size_t astr;
        if (c < xchunks) { asrc = (const char*)xpart + (size_t)c * 128; astr = (size_t)xstride * 2; }
        else { asrc = (const char*)hpart + (size_t)(c - xchunks) * 128; astr = (size_t)hstride * 2; }
        const char* bsrc = (const char*)wbase
                         + ((size_t)tile * 128 * wKc + (size_t)c * 64) * 2;
        const size_t bstr = (size_t)wKc * 2;
        #pragma unroll
        for (int i = 0; i < 4; i++) {
            int g = i * 256 + tid;
            int row = g >> 3, col = g & 7;
            uint32_t off = (uint32_t)(row * 128 + col * 16);
            cpasync16(abase + SW128(off), asrc + (size_t)row * astr + col * 16);
            cpasync16(bbase + SW128(off), bsrc + (size_t)row * bstr + col * 16);
        }
        asm volatile("cp.async.commit_group;" ::: "memory");
    };

    // protect stage buffers from the previous item's readers
    __syncthreads();

    load_stage(c0);
    if (c0 + 1 < c1) load_stage(c0 + 1);

    for (int c = c0; c < c1; c++) {
        if (c + 1 < c1) waitgrp<1>(); else waitgrp<0>();
        __syncthreads();                 // stage c visible; mma(c-1) done by all
        if (c + 2 < c1) load_stage(c + 2);   // overwrites slot (c-1)%3 — safe

        uint32_t abase = sb + (uint32_t)(c % 3) * STAGE_BYTES;
        uint32_t bbase = abase + 16384;
        #pragma unroll
        for (int ksi = 0; ksi < 4; ksi++) {
            int kb = ksi * 32 + (lane >> 4) * 16;
            uint32_t af[4][4];
            #pragma unroll
            for (int mt = 0; mt < 4; mt++) {
                uint32_t off = (uint32_t)((m_warp + mt * 16 + (lane & 15)) * 128 + kb);
                ldm_x4(af[mt][0], af[mt][1], af[mt][2], af[mt][3], abase + SW128(off));
            }
            uint32_t bf[4][2];
            #pragma unroll
            for (int np = 0; np < 2; np++) {
                uint32_t off = (uint32_t)((n_warp + np * 16 + (lane & 15)) * 128 + kb);
                uint32_t r0, r1, r2, r3;
                ldm_x4(r0, r1, r2, r3, bbase + SW128(off));
                bf[np * 2][0] = r0; bf[np * 2 + 1][0] = r1;
                bf[np * 2][1] = r2; bf[np * 2 + 1][1] = r3;
            }
            #pragma unroll
            for (int mt = 0; mt < 4; mt++)
                #pragma unroll
                for (int nt = 0; nt < 4; nt++)
                    mma16816(acc[mt][nt], af[mt][0], af[mt][1], af[mt][2], af[mt][3],
                             bf[nt][0], bf[nt][1]);
        }
    }

    int hrow = lane >> 2, head = lane & 3;
    #pragma unroll
    for (int mt = 0; mt < 4; mt++) {
        #pragma unroll
        for (int nt = 0; nt < 4; nt++) {
            int col = (warpcol * 4 + nt) * 4 + head;
            int r0 = m_warp + mt * 16 + hrow;
            if (warprow == 0) {
                P[r0 * 64 + col] = acc[mt][nt][0] + acc[mt][nt][1];
                P[(r0 + 8) * 64 + col] = acc[mt][nt][2] + acc[mt][nt][3];
            } else {
                P[r0 * 64 + col] = acc[mt][nt][0];
                P[(r0 + 8) * 64 + col] = acc[mt][nt][2];
            }
        }
    }
}

__device__ __forceinline__ void combine_q(
    int tid, const float* Pb, int tile, int quarter, int ks, int N, float ts,
    const float* __restrict__ bg, const float* __restrict__ bh,
    const float* __restrict__ bfg, const float* __restrict__ bfh,
    __nv_bfloat16* znx, int znx_stride,
    __nv_bfloat16* zsh, int zsh_stride,
    float* yp, float* hfp, int hoff)
{
    int pair = quarter * 256 + tid;
    int b = pair >> 4;
    int jj = pair & 15;
    int j = tile * 16 + jj;
    if (j >= N) return;
    float4 h4 = make_float4(0.f, 0.f, 0.f, 0.f);
    float4 l4 = make_float4(0.f, 0.f, 0.f, 0.f);
    for (int s = 0; s < ks; s++) {
        float4 a = __ldcg((const float4*)(Pb + (size_t)s * (128 * 64) + b * 64 + jj * 4));
        float4 c = __ldcg((const float4*)(Pb + (size_t)s * (128 * 64) + (b + 64) * 64 + jj * 4));
        h4.x += a.x; h4.y += a.y; h4.z += a.z; h4.w += a.w;
        l4.x += c.x; l4.y += c.y; l4.z += c.z; l4.w += c.w;
    }
    float a0 = h4.x + l4.x;
    float a1 = h4.y + l4.y;
    float a2 = h4.z + l4.z;
    float a3 = h4.w + l4.w;
    float g    = tanhf(a0 + bg[j]);
    float hh   = tanhf(a1 + bh[j]);
    float pre  = (a2 + bfg[j]) + ts * (a3 + bfh[j]);
    float gate = 1.f / (1.f + expf(-pre));
    float o    = g * (1.f - gate) + hh * gate;
    __nv_bfloat16 ohi = __float2bfloat16(o);
    __nv_bfloat16 olo = __float2bfloat16(o - __bfloat162float(ohi));
    if (znx) {
        znx[(size_t)b * znx_stride + j] = ohi;
        znx[(size_t)(b + 64) * znx_stride + j] = olo;
    }
    zsh[(size_t)b * zsh_stride + j] = ohi;
    zsh[(size_t)(b + 64) * zsh_stride + j] = olo;
    if (yp)  yp[(size_t)b * (SEQ * MOTOR) + j] = o;
    if (hfp) hfp[(size_t)b * NUNITS + hoff + j] = o;
}

__global__ void __launch_bounds__(256, 2)
scan_kernel(int nb, const float* __restrict__ tsp,
            const float* __restrict__ bg1, const float* __restrict__ bh1,
            const float* __restrict__ bfg1, const float* __restrict__ bfh1,
            const float* __restrict__ bg2, const float* __restrict__ bh2,
            const float* __restrict__ bfg2, const float* __restrict__ bfh2,
            const float* __restrict__ bg3, const float* __restrict__ bh3,
            const float* __restrict__ bfg3, const float* __restrict__ bfh3,
            float* __restrict__ out)
{
    extern __shared__ char smem[];
    const uint32_t sb = s2u32(smem);
    const int tid = threadIdx.x;
    const int bid = blockIdx.x;
    int target = 0;

    for (int p = 0; p < NPH; p++) {
        const int s1 = p, s2 = p - 1, s3 = p - 2;
        const bool a1 = (s1 < SEQ);
        const bool a2 = (s2 >= 0 && s2 < SEQ);
        const bool a3 = (s3 >= 0 && s3 < SEQ);
        const int n1 = a1 ? I1 : 0;
        const int n2 = a2 ? I2 : 0;
        const int n3 = a3 ? I3 : 0;
        const int total = n1 + n2 + n3;

        // ---- compute phase: split-K partials (strided schedule) ----
        for (int it = bid; it < total; it += nb) {
            if (it < n1) {
                int tile = it / KS1, split = it % KS1;
                compute_partial(sb, tid,
                    g_x1 + (size_t)s1 * 128 * IN_F, IN_F, XCH1,
                    g_z1h[s1 & 1], HPAD1, HCH1,
                    g_wb1, KC1, tile, split, KS1,
                    g_part + (size_t)(SLOT1 + it) * (128 * 64));
            } else if (it < n1 + n2) {
                int li = it - n1;
                int tile = li / KS2, split = li % KS2;
                compute_partial(sb, tid,
                    g_z2x, XPAD2, XCH2,
                    g_z2h[s2 & 1], HPAD2, HCH2,
                    g_wb2, KC2, tile, split, KS2,
                    g_part + (size_t)(SLOT2 + li) * (128 * 64));
            } else {
                int li = it - n1 - n2;
                int tile = li / KS3, split = li % KS3;
                compute_partial(sb, tid,
                    g_z3x, XPAD3, XCH3,
                    g_z3h[s3 & 1], HPAD3, HCH3,
                    g_wb3, KC3, tile, split, KS3,
                    g_part + (size_t)(SLOT3 + li) * (128 * 64));
            }
        }
        gbar(bid, tid, ++target, nb);

        // ---- combine phase ----
        const int c1n = a1 ? JT1 * 4 : 0;
        const int c2n = a2 ? JT2 * 4 : 0;
        const int c3n = a3 ? JT3 * 4 : 0;
        const int ctotal = c1n + c2n + c3n;
        for (int it = bid; it < ctotal; it += nb) {
            if (it < c1n) {
                int tile = it >> 2, q = it & 3;
                combine_q(tid, g_part + (size_t)(SLOT1 + tile * KS1) * (128 * 64),
                          tile, q, KS1, INTER, tsp[s1], bg1, bh1, bfg1, bfh1,
                          g_z2x, XPAD2, g_z1h[(s1 + 1) & 1], HPAD1,
                          nullptr, (s1 == SEQ - 1) ? (out + YSZ) : nullptr, 0);
            } else if (it < c1n + c2n) {
                int li = it - c1n;
                int tile = li >> 2, q = li & 3;
                combine_q(tid, g_part + (size_t)(SLOT2 + tile * KS2) * (128 * 64),
                          tile, q, KS2, CMD, tsp[s2], bg2, bh2, bfg2, bfh2,
                          g_z3x, XPAD3, g_z2h[(s2 + 1) & 1], HPAD2,
                          nullptr, (s2 == SEQ - 1) ? (out + YSZ) : nullptr, INTER);
            } else {
                int li = it - c1n - c2n;
                int tile = li >> 2, q = li & 3;
                combine_q(tid, g_part + (size_t)(SLOT3 + tile * KS3) * (128 * 64),
                          tile, q, KS3, MOTOR, tsp[s3], bg3, bh3, bfg3, bfh3,
                          nullptr, 0, g_z3h[(s3 + 1) & 1], HPAD3,
                          out + (size_t)s3 * MOTOR,
                          (s3 == SEQ - 1) ? (out + YSZ) : nullptr, INTER + CMD);
            }
        }
        gbar(bid, tid, ++target, nb);
    }
}

// ---------------- host ----------------
extern "C" void kernel_launch(void* const* d_in, const int* in_sizes, int n_in,
                              void* d_out, int out_size)
{
    const float* x   = (const float*)d_in[0];
    const float* h0  = (const float*)d_in[1];
    const float* ts  = (const float*)d_in[2];
    const float *Wg1=(const float*)d_in[3], *Wh1=(const float*)d_in[4],
                *Wfg1=(const float*)d_in[5], *Wfh1=(const float*)d_in[6],
                *bg1=(const float*)d_in[7], *bh1=(const float*)d_in[8],
                *bfg1=(const float*)d_in[9], *bfh1=(const float*)d_in[10],
                *m1=(const float*)d_in[11];
    const float *Wg2=(const float*)d_in[12], *Wh2=(const float*)d_in[13],
                *Wfg2=(const float*)d_in[14], *Wfh2=(const float*)d_in[15],
                *bg2=(const float*)d_in[16], *bh2=(const float*)d_in[17],
                *bfg2=(const float*)d_in[18], *bfh2=(const float*)d_in[19],
                *m2=(const float*)d_in[20];
    const float *Wg3=(const float*)d_in[21], *Wh3=(const float*)d_in[22],
                *Wfg3=(const float*)d_in[23], *Wfh3=(const float*)d_in[24],
                *bg3=(const float*)d_in[25], *bh3=(const float*)d_in[26],
                *bfg3=(const float*)d_in[27], *bfh3=(const float*)d_in[28],
                *m3=(const float*)d_in[29];
    float* out = (float*)d_out;

    __nv_bfloat16 *x1, *z1h, *z2h, *z3h;
    cudaGetSymbolAddress((void**)&x1,  g_x1);
    cudaGetSymbolAddress((void**)&z1h, g_z1h);
    cudaGetSymbolAddress((void**)&z2h, g_z2h);
    cudaGetSymbolAddress((void**)&z3h, g_z3h);

    cudaFuncSetAttribute(scan_kernel, cudaFuncAttributeMaxDynamicSharedMemorySize,
                         SMEM_TOTAL);

    int nper = 1, nsm = 148;
    cudaOccupancyMaxActiveBlocksPerMultiprocessor(&nper, scan_kernel, 256, SMEM_TOTAL);
    cudaDeviceGetAttribute(&nsm, cudaDevAttrMultiProcessorCount, 0);
    if (nper < 1) nper = 1;
    int nb = nper * nsm;
    if (nb > MAXGRID) nb = MAXGRID;

    prep_w_all<<<(JT1 + JT2 + JT3) * 64, 256>>>(Wg1, Wh1, Wfg1, Wfh1, m1,
                                                Wg2, Wh2, Wfg2, Wfh2, m2,
                                                Wg3, Wh3, Wfg3, Wfh3, m3);
    prep_x_kernel<<<(BATCH * SEQ * IN_F) / 256, 256>>>(x, x1);
    prep_h0_kernel<<<(BATCH * NUNITS) / 256, 256>>>(h0, z1h, z2h, z3h);

    scan_kernel<<<nb, 256, SMEM_TOTAL>>>(nb, ts,
        bg1, bh1, bfg1, bfh1, bg2, bh2, bfg2, bfh2, bg3, bh3, bfg3, bfh3, out);

    reset_kernel<<<1, 512>>>();
}

// round 17
// speedup vs baseline: 1.3489x; 1.0734x over previous
#include <cuda_runtime.h>
#include <cuda_bf16.h>
#include <math.h>
#include <stdint.h>

// LiquidNCPNetwork persistent kernel. R17: dead-quadrant elimination.
// Per 32 output cols: type A GEMM [z_hi;z_lo](128) x W_hi-tile(128 rows),
// type B GEMM z_hi(64) x W_lo-tile(128 rows). Same 3-term split math as
// R6-R16 (drop lo*lo). Cells pipelined across steps; 2 barriers/phase;
// single-sync chunk mainloop.

#define BATCH  64
#define SEQ    32
#define IN_F   512
#define INTER  1229
#define CMD    819
#define MOTOR  512
#define NUNITS 2560
#define YSZ    (BATCH * SEQ * MOTOR)

#define HPAD1 1280
#define KC1   1792
#define XCH1  8
#define HCH1  20
#define XPAD2 1280
#define HPAD2 832
#define KC2   2112
#define XCH2  20
#define HCH2  13
#define XPAD3 832
#define HPAD3 512
#define KC3   1344
#define XCH3  13
#define HCH3  8

#define JTA1 39   // ceil(1229/32)
#define JTA2 26   // ceil(819/32)
#define JTA3 16   // 512/32
#define KSA1 4
#define KSA2 4
#define KSA3 3
#define KSB1 2
#define KSB2 2
#define KSB3 2
#define NA1 (JTA1 * KSA1)   // 156
#define NA2 (JTA2 * KSA2)   // 104
#define NA3 (JTA3 * KSA3)   // 48
#define NB1 (JTA1 * KSB1)   // 78
#define NB2 (JTA2 * KSB2)   // 52
#define NB3 (JTA3 * KSB3)   // 32
#define ASL1 0
#define ASL2 NA1
#define ASL3 (NA1 + NA2)
#define NASL (NA1 + NA2 + NA3)      // 308
#define BSL1 0
#define BSL2 NB1
#define BSL3 (NB1 + NB2)
#define NBSLOT (NB1 + NB2 + NB3)    // 162
#define NPH (SEQ + 2)
#define MAXGRID 512
#define NBSL 16

// weights: [tile][part(0=hi,1=lo)][128 rows = jj*4+head][Kc] bf16
__device__ __align__(1024) __nv_bfloat16 g_wb1[(size_t)JTA1 * 2 * 128 * KC1];
__device__ __align__(1024) __nv_bfloat16 g_wb2[(size_t)JTA2 * 2 * 128 * KC2];
__device__ __align__(1024) __nv_bfloat16 g_wb3[(size_t)JTA3 * 2 * 128 * KC3];
__device__ __align__(1024) __nv_bfloat16 g_x1[(size_t)SEQ * 128 * IN_F];
__device__ __align__(1024) __nv_bfloat16 g_z1h[2][128 * HPAD1];
__device__ __align__(1024) __nv_bfloat16 g_z2x[128 * XPAD2];
__device__ __align__(1024) __nv_bfloat16 g_z2h[2][128 * HPAD2];
__device__ __align__(1024) __nv_bfloat16 g_z3x[128 * XPAD3];
__device__ __align__(1024) __nv_bfloat16 g_z3h[2][128 * HPAD3];
__device__ __align__(16) float g_partA[(size_t)NASL * 128 * 128];
__device__ __align__(16) float g_partB[(size_t)NBSLOT * 64 * 128];
__device__ int g_arr[NBSL * 32];
__device__ int g_top;
__device__ volatile int g_release;

#define SW128(o) ((o) ^ (((o) >> 3) & 0x70))
#define STAGE_BYTES 32768
#define SMEM_TOTAL  (3 * STAGE_BYTES)

__device__ __forceinline__ uint32_t s2u32(const void* p) {
    uint32_t a;
    asm("{ .reg .u64 t; cvta.to.shared.u64 t, %1; cvt.u32.u64 %0, t; }" : "=r"(a) : "l"(p));
    return a;
}
__device__ __forceinline__ void cpasync16(uint32_t s, const void* g) {
    asm volatile("cp.async.cg.shared.global [%0], [%1], 16;" :: "r"(s), "l"(g));
}
template<int N> __device__ __forceinline__ void waitgrp() {
    asm volatile("cp.async.wait_group %0;" :: "n"(N) : "memory");
}
__device__ __forceinline__ void ldm_x4(uint32_t& r0, uint32_t& r1, uint32_t& r2,
                                       uint32_t& r3, uint32_t addr) {
    asm volatile("ldmatrix.sync.aligned.m8n8.x4.shared.b16 {%0,%1,%2,%3}, [%4];"
                 : "=r"(r0), "=r"(r1), "=r"(r2), "=r"(r3) : "r"(addr));
}
__device__ __forceinline__ void mma16816(float* c, uint32_t a0, uint32_t a1, uint32_t a2,
                                         uint32_t a3, uint32_t b0, uint32_t b1) {
    asm volatile("mma.sync.aligned.m16n8k16.row.col.f32.bf16.bf16.f32 "
                 "{%0,%1,%2,%3}, {%4,%5,%6,%7}, {%8,%9}, {%0,%1,%2,%3};"
                 : "+f"(c[0]), "+f"(c[1]), "+f"(c[2]), "+f"(c[3])
                 : "r"(a0), "r"(a1), "r"(a2), "r"(a3), "r"(b0), "r"(b1));
}

__device__ __forceinline__ void gbar(int bid, int tid, int target, int nb) {
    __syncthreads();
    if (tid == 0) {
        __threadfence();
        int slot = bid & (NBSL - 1);
        int cnt = (nb - slot + NBSL - 1) / NBSL;
        int prev = atomicAdd(&g_arr[slot * 32], 1);
        if (prev == target * cnt - 1) {
            int pt = atomicAdd(&g_top, 1);
            if (pt == target * NBSL - 1) g_release = target;
        }
        while (g_release < target) { }
        __threadfence();
    }
    __syncthreads();
}

// ---------------- prep kernels ----------------
// one block per (tile, n-row); writes hi and lo parts for that row.
__global__ void prep_w_all(
    const float* __restrict__ Wg1, const float* __restrict__ Wh1,
    const float* __restrict__ Wfg1, const float* __restrict__ Wfh1,
    const float* __restrict__ M1,
    const float* __restrict__ Wg2, const float* __restrict__ Wh2,
    const float* __restrict__ Wfg2, const float* __restrict__ Wfh2,
    const float* __restrict__ M2,
    const float* __restrict__ Wg3, const float* __restrict__ Wh3,
    const float* __restrict__ Wfg3, const float* __restrict__ Wfh3,
    const float* __restrict__ M3)
{
    int blk = blockIdx.x;
    const float *Wg, *Wh, *Wfg, *Wfh, *M;
    __nv_bfloat16* dst;
    int N, Korig, xvalid, xpad, hvalid, Kc;
    if (blk < JTA1 * 128) {
        Wg = Wg1; Wh = Wh1; Wfg = Wfg1; Wfh = Wfh1; M = M1; dst = g_wb1;
        N = INTER; Korig = IN_F + INTER; xvalid = IN_F; xpad = IN_F;
        hvalid = INTER; Kc = KC1;
    } else if (blk < (JTA1 + JTA2) * 128) {
        blk -= JTA1 * 128;
        Wg = Wg2; Wh = Wh2; Wfg = Wfg2; Wfh = Wfh2; M = M2; dst = g_wb2;
        N = CMD; Korig = INTER + CMD; xvalid = INTER; xpad = XPAD2;
        hvalid = CMD; Kc = KC2;
    } else {
        blk -= (JTA1 + JTA2) * 128;
        Wg = Wg3; Wh = Wh3; Wfg = Wfg3; Wfh = Wfh3; M = M3; dst = g_wb3;
        N = MOTOR; Korig = CMD + MOTOR; xvalid = CMD; xpad = XPAD3;
        hvalid = MOTOR; Kc = KC3;
    }
    int tile = blk >> 7;
    int n = blk & 127;
    int jj = n >> 2, head = n & 3;
    int j = tile * 32 + jj;
    const float* W = (head == 0) ? Wg : (head == 1) ? Wh : (head == 2) ? Wfg : Wfh;
    __nv_bfloat16* d_hi = dst + ((size_t)(tile * 2) * 128 + n) * Kc;
    __nv_bfloat16* d_lo = dst + ((size_t)(tile * 2 + 1) * 128 + n) * Kc;
    bool jok = (j < N);
    for (int k = threadIdx.x; k < Kc; k += 256) {
        float v = 0.f;
        if (jok) {
            int kin; bool ok;
            if (k < xpad) { kin = k; ok = (k < xvalid); }
            else { int hk = k - xpad; kin = xvalid + hk; ok = (hk < hvalid); }
            if (ok) v = W[(size_t)j * Korig + kin] * M[(size_t)j * Korig + kin];
        }
        __nv_bfloat16 hi = __float2bfloat16(v);
        d_hi[k] = hi;
        d_lo[k] = __float2bfloat16(v - __bfloat162float(hi));
    }
}

__global__ void prep_x_kernel(const float* __restrict__ x, __nv_bfloat16* __restrict__ dst)
{
    int idx = blockIdx.x * 256 + threadIdx.x;
    int b = idx >> 14, r = idx & 16383, s = r >> 9, f = r & 511;
    float v = x[idx];
    __nv_bfloat16 hi = __float2bfloat16(v);
    size_t base = (size_t)s * 128 * 512;
    dst[base + (size_t)b * 512 + f] = hi;
    dst[base + (size_t)(b + 64) * 512 + f] = __float2bfloat16(v - __bfloat162float(hi));
}

__global__ void prep_h0_kernel(const float* __restrict__ h0, __nv_bfloat16* __restrict__ z1,
                               __nv_bfloat16* __restrict__ z2, __nv_bfloat16* __restrict__ z3)
{
    int idx = blockIdx.x * 256 + threadIdx.x;
    int b = idx / NUNITS, u = idx % NUNITS;
    float v = h0[idx];
    __nv_bfloat16 hi = __float2bfloat16(v);
    __nv_bfloat16 lo = __float2bfloat16(v - __bfloat162float(hi));
    if (u < INTER)            { z1[(size_t)b*HPAD1+u] = hi; z1[(size_t)(b+64)*HPAD1+u] = lo; }
    else if (u < INTER + CMD) { int c = u - INTER;
                                z2[(size_t)b*HPAD2+c] = hi; z2[(size_t)(b+64)*HPAD2+c] = lo; }
    else                      { int c = u - INTER - CMD;
                                z3[(size_t)b*HPAD3+c] = hi; z3[(size_t)(b+64)*HPAD3+c] = lo; }
}

__global__ void reset_kernel() {
    int i = threadIdx.x;
    if (i < NBSL * 32) g_arr[i] = 0;
    if (i == 0) { g_top = 0; g_release = 0; }
}

// ---------------- persistent scan kernel ----------------
// MT=4: M=128 (rows = [hi;lo]); MT=2: M=64 (hi only). N always 128 B-rows.
template<int MT>
__device__ __forceinline__ void compute_partial(
    uint32_t sb, int tid,
    const __nv_bfloat16* xpart, int xstride, int xchunks,
    const __nv_bfloat16* hpart, int hstride, int hchunks,
    const __nv_bfloat16* wtile,   // [128][Kc] for the chosen part
    int wKc, int split, int ks, float* P)
{
    const int lane = tid & 31;
    const int wid  = tid >> 5;
    const int warprow = wid >> 2;
    const int warpcol = wid & 3;
    const int m_warp = warprow * (MT * 16);
    const int n_warp = warpcol * 32;
    const int C = xchunks + hchunks;
    const int c0 = (C * split) / ks;
    const int c1 = (C * (split + 1)) / ks;

    float acc[MT][4][4];
    #pragma unroll
    for (int mt = 0; mt < MT; mt++)
        #pragma unroll
        for (int nt = 0; nt < 4; nt++)
            #pragma unroll
            for (int i = 0; i < 4; i++) acc[mt][nt][i] = 0.f;

    auto load_stage = [&](int c) {
        uint32_t abase = sb + (uint32_t)(c % 3) * STAGE_BYTES;
        uint32_t bbase = abase + 16384;
        const char* asrc; size_t astr;
        if (c < xchunks) { asrc = (const char*)xpart + (size_t)c * 128; astr = (size_t)xstride * 2; }
        else { asrc = (const char*)hpart + (size_t)(c - xchunks) * 128; astr = (size_t)hstride * 2; }
        const char* bsrc = (const char*)wtile + (size_t)c * 128;
        const size_t bstr = (size_t)wKc * 2;
        #pragma unroll
        for (int i = 0; i < MT; i++) {        // A: MT*32 rows x 8 16B-cols
            int g = i * 256 + tid;
            int row = g >> 3, col = g & 7;
            uint32_t off = (uint32_t)(row * 128 + col * 16);
            cpasync16(abase + SW128(off), asrc + (size_t)row * astr + col * 16);
        }
        #pragma unroll
        for (int i = 0; i < 4; i++) {         // B: 128 rows x 8 16B-cols
            int g = i * 256 + tid;
            int row = g >> 3, col = g & 7;
            uint32_t off = (uint32_t)(row * 128 + col * 16);
            cpasync16(bbase + SW128(off), bsrc + (size_t)row * bstr + col * 16);
        }
        asm volatile("cp.async.commit_group;" ::: "memory");
    };

    __syncthreads();   // protect stages from previous item's readers

    load_stage(c0);
    if (c0 + 1 < c1) load_stage(c0 + 1);

    for (int c = c0; c < c1; c++) {
        if (c + 1 < c1) waitgrp<1>(); else waitgrp<0>();
        __syncthreads();
        if (c + 2 < c1) load_stage(c + 2);

        uint32_t abase = sb + (uint32_t)(c % 3) * STAGE_BYTES;
        uint32_t bbase = abase + 16384;
        #pragma unroll
        for (int ksi = 0; ksi < 4; ksi++) {
            int kb = ksi * 32 + (lane >> 4) * 16;
            uint32_t af[MT][4];
            #pragma unroll
            for (int mt = 0; mt < MT; mt++) {
                uint32_t off = (uint32_t)((m_warp + mt * 16 + (lane & 15)) * 128 + kb);
                ldm_x4(af[mt][0], af[mt][1], af[mt][2], af[mt][3], abase + SW128(off));
            }
            uint32_t bf[4][2];
            #pragma unroll
            for (int np = 0; np < 2; np++) {
                uint32_t off = (uint32_t)((n_warp + np * 16 + (lane & 15)) * 128 + kb);
                uint32_t r0, r1, r2, r3;
                ldm_x4(r0, r1, r2, r3, bbase + SW128(off));
                bf[np * 2][0] = r0; bf[np * 2 + 1][0] = r1;
                bf[np * 2][1] = r2; bf[np * 2 + 1][1] = r3;
            }
            #pragma unroll
            for (int mt = 0; mt < MT; mt++)
                #pragma unroll
                for (int nt = 0; nt < 4; nt++)
                    mma16816(acc[mt][nt], af[mt][0], af[mt][1], af[mt][2], af[mt][3],
                             bf[nt][0], bf[nt][1]);
        }
    }

    // write partial: P[M rows][128 cols], col = B-row index
    int hrow = lane >> 2;
    int cb = n_warp + (lane & 3) * 2;
    #pragma unroll
    for (int mt = 0; mt < MT; mt++) {
        #pragma unroll
        for (int nt = 0; nt < 4; nt++) {
            int c = cb + nt * 8;
            int r0 = m_warp + mt * 16 + hrow;
            *(float2*)&P[(size_t)r0 * 128 + c] = make_float2(acc[mt][nt][0], acc[mt][nt][1]);
            *(float2*)&P[(size_t)(r0 + 8) * 128 + c] = make_float2(acc[mt][nt][2], acc[mt][nt][3]);
        }
    }
}

// combine one octant (256 of 2048 outputs) of a 32-col tile
__device__ __forceinline__ void combine_o(
    int tid, const float* PAb, const float* PBb, int ksa, int ksb,
    int tile, int oct, int N, float ts,
    const float* __restrict__ bg, const float* __restrict__ bh,
    const float* __restrict__ bfg, const float* __restrict__ bfh,
    __nv_bfloat16* znx, int znx_stride,
    __nv_bfloat16* zsh, int zsh_stride,
    float* yp, float* hfp, int hoff)
{
    int pair = oct * 256 + tid;
    int b = pair >> 5;
    int jj = pair & 31;
    int j = tile * 32 + jj;
    if (j >= N) return;
    float4 a4 = make_float4(0.f, 0.f, 0.f, 0.f);
    for (int s = 0; s < ksa; s++) {
        const float* P = PAb + (size_t)s * (128 * 128);
        float4 u = __ldcg((const float4*)(P + (size_t)b * 128 + jj * 4));
        float4 v = __ldcg((const float4*)(P + (size_t)(b + 64) * 128 + jj * 4));
        a4.x += u.x + v.x; a4.y += u.y + v.y;
        a4.z += u.z + v.z; a4.w += u.w + v.w;
    }
    for (int s = 0; s < ksb; s++) {
        const float* P = PBb + (size_t)s * (64 * 128);
        float4 u = __ldcg((const float4*)(P + (size_t)b * 128 + jj * 4));
        a4.x += u.x; a4.y += u.y; a4.z += u.z; a4.w += u.w;
    }
    float g    = tanhf(a4.x + bg[j]);
    float hh   = tanhf(a4.y + bh[j]);
    float pre  = (a4.z + bfg[j]) + ts * (a4.w + bfh[j]);
    float gate = 1.f / (1.f + expf(-pre));
    float o    = g * (1.f - gate) + hh * gate;
    __nv_bfloat16 ohi = __float2bfloat16(o);
    __nv_bfloat16 olo = __float2bfloat16(o - __bfloat162float(ohi));
    if (znx) {
        znx[(size_t)b * znx_stride + j] = ohi;
        znx[(size_t)(b + 64) * znx_stride + j] = olo;
    }
    zsh[(size_t)b * zsh_stride + j] = ohi;
    zsh[(size_t)(b + 64) * zsh_stride + j] = olo;
    if (yp)  yp[(size_t)b * (SEQ * MOTOR) + j] = o;
    if (hfp) hfp[(size_t)b * NUNITS + hoff + j] = o;
}

__global__ void __launch_bounds__(256, 2)
scan_kernel(int nb, const float* __restrict__ tsp,
            const float* __restrict__ bg1, const float* __restrict__ bh1,
            const float* __restrict__ bfg1, const float* __restrict__ bfh1,
            const float* __restrict__ bg2, const float* __restrict__ bh2,
            const float* __restrict__ bfg2, const float* __restrict__ bfh2,
            const float* __restrict__ bg3, const float* __restrict__ bh3,
            const float* __restrict__ bfg3, const float* __restrict__ bfh3,
            float* __restrict__ out)
{
    extern __shared__ char smem[];
    const uint32_t sb = s2u32(smem);
    const int tid = threadIdx.x;
    const int bid = blockIdx.x;
    int target = 0;

    for (int p = 0; p < NPH; p++) {
        const int s1 = p, s2 = p - 1, s3 = p - 2;
        const bool a1 = (s1 < SEQ);
        const bool a2 = (s2 >= 0 && s2 < SEQ);
        const bool a3 = (s3 >= 0 && s3 < SEQ);
        const int na1 = a1 ? NA1 : 0, na2 = a2 ? NA2 : 0, na3 = a3 ? NA3 : 0;
        const int nb1 = a1 ? NB1 : 0, nb2 = a2 ? NB2 : 0, nb3 = a3 ? NB3 : 0;
        const int total = na1 + na2 + na3 + nb1 + nb2 + nb3;

        // ---- compute phase ----
        for (int it = bid; it < total; it += nb) {
            int t = it;
            if (t < na1) {
                int tile = t / KSA1, split = t % KSA1;
                compute_partial<4>(sb, tid,
                    g_x1 + (size_t)s1 * 128 * IN_F, IN_F, XCH1,
                    g_z1h[s1 & 1], HPAD1, HCH1,
                    g_wb1 + (size_t)(tile * 2) * 128 * KC1, KC1, split, KSA1,
                    g_partA + (size_t)(ASL1 + t) * (128 * 128));
                continue;
            }
            t -= na1;
            if (t < na2) {
                int tile = t / KSA2, split = t % KSA2;
                compute_partial<4>(sb, tid,
                    g_z2x, XPAD2, XCH2,
                    g_z2h[s2 & 1], HPAD2, HCH2,
                    g_wb2 + (size_t)(tile * 2) * 128 * KC2, KC2, split, KSA2,
                    g_partA + (size_t)(ASL2 + t) * (128 * 128));
                continue;
            }
            t -= na2;
            if (t < na3) {
                int tile = t / KSA3, split = t % KSA3;
                compute_partial<4>(sb, tid,
                    g_z3x, XPAD3, XCH3,
                    g_z3h[s3 & 1], HPAD3, HCH3,
                    g_wb3 + (size_t)(tile * 2) * 128 * KC3, KC3, split, KSA3,
                    g_partA + (size_t)(ASL3 + t) * (128 * 128));
                continue;
            }
            t -= na3;
            if (t < nb1) {
                int tile = t / KSB1, split = t % KSB1;
                compute_partial<2>(sb, tid,
                    g_x1 + (size_t)s1 * 128 * IN_F, IN_F, XCH1,
                    g_z1h[s1 & 1], HPAD1, HCH1,
                    g_wb1 + (size_t)(tile * 2 + 1) * 128 * KC1, KC1, split, KSB1,
                    g_partB + (size_t)(BSL1 + t) * (64 * 128));
                continue;
            }
            t -= nb1;
            if (t < nb2) {
                int tile = t / KSB2, split = t % KSB2;
                compute_partial<2>(sb, tid,
                    g_z2x, XPAD2, XCH2,
                    g_z2h[s2 & 1], HPAD2, HCH2,
                    g_wb2 + (size_t)(tile * 2 + 1) * 128 * KC2, KC2, split, KSB2,
                    g_partB + (size_t)(BSL2 + t) * (64 * 128));
                continue;
            }
            t -= nb2;
            {
                int tile = t / KSB3, split = t % KSB3;
                compute_partial<2>(sb, tid,
                    g_z3x, XPAD3, XCH3,
                    g_z3h[s3 & 1], HPAD3, HCH3,
                    g_wb3 + (size_t)(tile * 2 + 1) * 128 * KC3, KC3, split, KSB3,
                    g_partB + (size_t)(BSL3 + t) * (64 * 128));
            }
        }
        gbar(bid, tid, ++target, nb);

        // ---- combine phase: 8 octants per 32-col tile ----
        const int c1n = a1 ? JTA1 * 8 : 0;
        const int c2n = a2 ? JTA2 * 8 : 0;
        const int c3n = a3 ? JTA3 * 8 : 0;
        const int ctotal = c1n + c2n + c3n;
        for (int it = bid; it < ctotal; it += nb) {
            if (it < c1n) {
                int tile = it >> 3, oct = it & 7;
                combine_o(tid,
                    g_partA + (size_t)(ASL1 + tile * KSA1) * (128 * 128),
                    g_partB + (size_t)(BSL1 + tile * KSB1) * (64 * 128),
                    KSA1, KSB1, tile, oct, INTER, tsp[s1], bg1, bh1, bfg1, bfh1,
                    g_z2x, XPAD2, g_z1h[(s1 + 1) & 1], HPAD1,
                    nullptr, (s1 == SEQ - 1) ? (out + YSZ) : nullptr, 0);
            } else if (it < c1n + c2n) {
                int li = it - c1n;
                int tile = li >> 3, oct = li & 7;
                combine_o(tid,
                    g_partA + (size_t)(ASL2 + tile * KSA2) * (128 * 128),
                    g_partB + (size_t)(BSL2 + tile * KSB2) * (64 * 128),
                    KSA2, KSB2, tile, oct, CMD, tsp[s2], bg2, bh2, bfg2, bfh2,
                    g_z3x, XPAD3, g_z2h[(s2 + 1) & 1], HPAD2,
                    nullptr, (s2 == SEQ - 1) ? (out + YSZ) : nullptr, INTER);
            } else {
                int li = it - c1n - c2n;
                int tile = li >> 3, oct = li & 7;
                combine_o(tid,
                    g_partA + (size_t)(ASL3 + tile * KSA3) * (128 * 128),
                    g_partB + (size_t)(BSL3 + tile * KSB3) * (64 * 128),
                    KSA3, KSB3, tile, oct, MOTOR, tsp[s3], bg3, bh3, bfg3, bfh3,
                    nullptr, 0, g_z3h[(s3 + 1) & 1], HPAD3,
                    out + (size_t)s3 * MOTOR,
                    (s3 == SEQ - 1) ? (out + YSZ) : nullptr, INTER + CMD);
            }
        }
        gbar(bid, tid, ++target, nb);
    }
}

// ---------------- host ----------------
extern "C" void kernel_launch(void* const* d_in, const int* in_sizes, int n_in,
                              void* d_out, int out_size)
{
    const float* x   = (const float*)d_in[0];
    const float* h0  = (const float*)d_in[1];
    const float* ts  = (const float*)d_in[2];
    const float *Wg1=(const float*)d_in[3], *Wh1=(const float*)d_in[4],
                *Wfg1=(const float*)d_in[5], *Wfh1=(const float*)d_in[6],
                *bg1=(const float*)d_in[7], *bh1=(const float*)d_in[8],
                *bfg1=(const float*)d_in[9], *bfh1=(const float*)d_in[10],
                *m1=(const float*)d_in[11];
    const float *Wg2=(const float*)d_in[12], *Wh2=(const float*)d_in[13],
                *Wfg2=(const float*)d_in[14], *Wfh2=(const float*)d_in[15],
                *bg2=(const float*)d_in[16], *bh2=(const float*)d_in[17],
                *bfg2=(const float*)d_in[18], *bfh2=(const float*)d_in[19],
                *m2=(const float*)d_in[20];
    const float *Wg3=(const float*)d_in[21], *Wh3=(const float*)d_in[22],
                *Wfg3=(const float*)d_in[23], *Wfh3=(const float*)d_in[24],
                *bg3=(const float*)d_in[25], *bh3=(const float*)d_in[26],
                *bfg3=(const float*)d_in[27], *bfh3=(const float*)d_in[28],
                *m3=(const float*)d_in[29];
    float* out = (float*)d_out;

    __nv_bfloat16 *x1, *z1h, *z2h, *z3h;
    cudaGetSymbolAddress((void**)&x1,  g_x1);
    cudaGetSymbolAddress((void**)&z1h, g_z1h);
    cudaGetSymbolAddress((void**)&z2h, g_z2h);
    cudaGetSymbolAddress((void**)&z3h, g_z3h);

    cudaFuncSetAttribute(scan_kernel, cudaFuncAttributeMaxDynamicSharedMemorySize,
                         SMEM_TOTAL);

    int nper = 1, nsm = 148;
    cudaOccupancyMaxActiveBlocksPerMultiprocessor(&nper, scan_kernel, 256, SMEM_TOTAL);
    cudaDeviceGetAttribute(&nsm, cudaDevAttrMultiProcessorCount, 0);
    if (nper < 1) nper = 1;
    int nb = nper * nsm;
    if (nb > MAXGRID) nb = MAXGRID;

    prep_w_all<<<(JTA1 + JTA2 + JTA3) * 128, 256>>>(Wg1, Wh1, Wfg1, Wfh1, m1,
                                                    Wg2, Wh2, Wfg2, Wfh2, m2,
                                                    Wg3, Wh3, Wfg3, Wfh3, m3);
    prep_x_kernel<<<(BATCH * SEQ * IN_F) / 256, 256>>>(x, x1);
    prep_h0_kernel<<<(BATCH * NUNITS) / 256, 256>>>(h0, z1h, z2h, z3h);

    scan_kernel<<<nb, 256, SMEM_TOTAL>>>(nb, ts,
        bg1, bh1, bfg1, bfh1, bg2, bh2, bfg2, bfh2, bg3, bh3, bfg3, bfh3, out);

    reset_kernel<<<1, 512>>>();
}